// round 1
// baseline (speedup 1.0000x reference)
#include <cuda_runtime.h>
#include <math.h>

#define Dm   2048
#define Sm   512
#define Hn   16
#define HKVn 4
#define DHn  128
#define Fn   2048
#define En   8

// ---------------- scratch (device globals; no allocation allowed) ----------------
__device__ float g_x[Sm*Dm];
__device__ float g_q[Sm*Dm];
__device__ float g_k[Sm*HKVn*DHn];
__device__ float g_v[Sm*HKVn*DHn];
__device__ float g_scores[Hn*Sm*Sm];
__device__ float g_attn[Sm*Dm];
__device__ float g_h[Sm*Dm];
__device__ float g_x2[Sm*Dm];
__device__ int   g_topidx[Sm];
__device__ float g_topscore[Sm];
__device__ int   g_cnt[En];
__device__ int   g_list[En*Sm];
__device__ float g_eg[Sm*Fn];
__device__ float g_eu[Sm*Fn];
__device__ float g_act[Sm*Fn];
__device__ float g_routed[Sm*Dm];
__device__ float g_gs[Sm*Fn];
__device__ float g_us[Sm*Fn];
__device__ float g_sact[Sm*Fn];
__device__ float g_shared[Sm*Dm];

// ---------------- small kernels ----------------
__global__ void rmsnorm_kernel(const float* __restrict__ in, const float* __restrict__ w,
                               float* __restrict__ out) {
    int t = blockIdx.x;
    const float* row = in + (size_t)t * Dm;
    float s = 0.f;
    for (int d = threadIdx.x; d < Dm; d += 256) { float v = row[d]; s += v * v; }
    __shared__ float red[256];
    red[threadIdx.x] = s; __syncthreads();
    for (int off = 128; off > 0; off >>= 1) {
        if (threadIdx.x < off) red[threadIdx.x] += red[threadIdx.x + off];
        __syncthreads();
    }
    float r = rsqrtf(red[0] / (float)Dm + 1e-5f);
    for (int d = threadIdx.x; d < Dm; d += 256)
        out[(size_t)t * Dm + d] = row[d] * r * w[d];
}

__global__ void rope_kernel(float* __restrict__ q, float* __restrict__ k,
                            const int* __restrict__ pos_ids) {
    int t = blockIdx.x;
    float p = (float)pos_ids[t];
    for (int idx = threadIdx.x; idx < (Hn + HKVn) * 64; idx += blockDim.x) {
        int head = idx >> 6;
        int i = idx & 63;
        float inv = powf(500000.0f, -(float)i / 64.0f);
        float f = p * inv;
        float sn, cs;
        sincosf(f, &sn, &cs);
        float* base;
        if (head < Hn) base = q + (size_t)t * Dm + head * DHn;
        else           base = k + (size_t)t * (HKVn * DHn) + (head - Hn) * DHn;
        float x1 = base[i], x2 = base[i + 64];
        base[i]      = x1 * cs - x2 * sn;
        base[i + 64] = x2 * cs + x1 * sn;
    }
}

__global__ void softmax_kernel(float* __restrict__ sc, const int* __restrict__ mask) {
    int i = blockIdx.x;   // query
    int h = blockIdx.y;   // head
    float* row = sc + ((size_t)h * Sm + i) * Sm;
    int tid = threadIdx.x;
    int j0 = tid, j1 = tid + 256;
    float s0 = (j0 <= i && mask[j0] > 0) ? row[j0] : -1e9f;
    float s1 = (j1 <= i && mask[j1] > 0) ? row[j1] : -1e9f;
    __shared__ float red[256];
    red[tid] = fmaxf(s0, s1); __syncthreads();
    for (int off = 128; off > 0; off >>= 1) {
        if (tid < off) red[tid] = fmaxf(red[tid], red[tid + off]);
        __syncthreads();
    }
    float m = red[0];
    __syncthreads();
    float e0 = expf(s0 - m), e1 = expf(s1 - m);
    red[tid] = e0 + e1; __syncthreads();
    for (int off = 128; off > 0; off >>= 1) {
        if (tid < off) red[tid] += red[tid + off];
        __syncthreads();
    }
    float inv = 1.f / red[0];
    row[j0] = e0 * inv;
    row[j1] = e1 * inv;
}

__global__ void router_kernel(const float* __restrict__ x2, const float* __restrict__ rw,
                              int* __restrict__ topidx, float* __restrict__ topscore) {
    int t = blockIdx.x;
    int w = threadIdx.x >> 5, lane = threadIdx.x & 31;
    float s = 0.f;
    for (int d = lane; d < Dm; d += 32)
        s += x2[(size_t)t * Dm + d] * rw[d * En + w];
    for (int off = 16; off; off >>= 1) s += __shfl_down_sync(0xffffffff, s, off);
    __shared__ float logits[En];
    if (lane == 0) logits[w] = s;
    __syncthreads();
    if (threadIdx.x == 0) {
        int best = 0; float bv = logits[0];
        for (int e = 1; e < En; e++) if (logits[e] > bv) { bv = logits[e]; best = e; }
        topidx[t] = best;
        topscore[t] = 1.f / (1.f + expf(-bv));
    }
}

__global__ void dispatch_kernel(const int* __restrict__ topidx) {
    int t = threadIdx.x;  // 512 threads
    if (t < En) g_cnt[t] = 0;
    __syncthreads();
    int e = topidx[t];
    int pos = atomicAdd(&g_cnt[e], 1);
    g_list[e * Sm + pos] = t;
}

__global__ void silumul_kernel(const float* __restrict__ g, const float* __restrict__ u,
                               float* __restrict__ out, int n) {
    int i = blockIdx.x * 256 + threadIdx.x;
    if (i < n) {
        float x = g[i];
        out[i] = (x / (1.f + expf(-x))) * u[i];
    }
}

__global__ void add3_kernel(const float* __restrict__ a, const float* __restrict__ b,
                            const float* __restrict__ c, float* __restrict__ out) {
    int i = blockIdx.x * 256 + threadIdx.x;
    out[i] = a[i] + b[i] + c[i];
}

// ---------------- GEMM tile machinery (64x64x16, 4x4/thread, 256 threads) -------
__device__ __forceinline__ void mm_accum(const float (*As)[20], const float (*Bs)[68],
                                         float acc[4][4], int tx, int ty) {
#pragma unroll
    for (int kk = 0; kk < 16; kk++) {
        float a[4];
#pragma unroll
        for (int i = 0; i < 4; i++) a[i] = As[ty * 4 + i][kk];
        float4 b = *(const float4*)(&Bs[kk][tx * 4]);
#pragma unroll
        for (int i = 0; i < 4; i++) {
            acc[i][0] += a[i] * b.x;
            acc[i][1] += a[i] * b.y;
            acc[i][2] += a[i] * b.z;
            acc[i][3] += a[i] * b.w;
        }
    }
}

// C[m,n] = sum_k A[m,k]*B[k,n]  (+ res[m,n]); tile fully in-bounds (all dims %64==0)
__global__ void sgemm_nn_kernel(const float* __restrict__ A, int lda,
                                const float* __restrict__ B, int ldb,
                                float* __restrict__ C, int ldc, int K,
                                const float* __restrict__ res) {
    __shared__ float As[64][20];
    __shared__ float Bs[16][68];
    int tid = threadIdx.x;
    const float* Ab = A + (size_t)blockIdx.y * 64 * lda;
    const float* Bb = B + blockIdx.x * 64;
    int a_m = tid >> 2, a_k = (tid & 3) * 4;
    int bk = (tid * 4) >> 6, bn = (tid * 4) & 63;
    float acc[4][4] = {};
    for (int k0 = 0; k0 < K; k0 += 16) {
        *(float4*)(&As[a_m][a_k]) = *(const float4*)(Ab + (size_t)a_m * lda + k0 + a_k);
        *(float4*)(&Bs[bk][bn])   = *(const float4*)(Bb + (size_t)(k0 + bk) * ldb + bn);
        __syncthreads();
        mm_accum(As, Bs, acc, tid & 15, tid >> 4);
        __syncthreads();
    }
    int tx = tid & 15, ty = tid >> 4;
    int r0 = blockIdx.y * 64 + ty * 4, c0 = blockIdx.x * 64 + tx * 4;
#pragma unroll
    for (int i = 0; i < 4; i++) {
        float4 o = make_float4(acc[i][0], acc[i][1], acc[i][2], acc[i][3]);
        if (res) {
            const float4 rv = *(const float4*)(res + (size_t)(r0 + i) * ldc + c0);
            o.x += rv.x; o.y += rv.y; o.z += rv.z; o.w += rv.w;
        }
        *(float4*)(C + (size_t)(r0 + i) * ldc + c0) = o;
    }
}

// scores[h,i,j] = (1/sqrt(128)) * sum_d q[i, h*128+d] * k[j, (h/4)*128+d]   (NT)
__global__ void scores_kernel(const float* __restrict__ q, const float* __restrict__ k,
                              float* __restrict__ sc) {
    int h = blockIdx.z;
    __shared__ float As[64][20];
    __shared__ float Bs[16][68];
    int tid = threadIdx.x;
    const float* Ab = q + (size_t)blockIdx.y * 64 * Dm + h * DHn;
    const float* Bb = k + (size_t)blockIdx.x * 64 * (HKVn * DHn) + (h >> 2) * DHn;
    int a_m = tid >> 2, a_k = (tid & 3) * 4;
    int bn = tid >> 2, bkk = (tid & 3) * 4;
    float acc[4][4] = {};
    for (int k0 = 0; k0 < DHn; k0 += 16) {
        *(float4*)(&As[a_m][a_k]) = *(const float4*)(Ab + (size_t)a_m * Dm + k0 + a_k);
        float4 bv = *(const float4*)(Bb + (size_t)bn * (HKVn * DHn) + k0 + bkk);
        Bs[bkk + 0][bn] = bv.x; Bs[bkk + 1][bn] = bv.y;
        Bs[bkk + 2][bn] = bv.z; Bs[bkk + 3][bn] = bv.w;
        __syncthreads();
        mm_accum(As, Bs, acc, tid & 15, tid >> 4);
        __syncthreads();
    }
    int tx = tid & 15, ty = tid >> 4;
    float* out = sc + (size_t)h * Sm * Sm;
    int r0 = blockIdx.y * 64 + ty * 4, c0 = blockIdx.x * 64 + tx * 4;
    const float scale = 0.0883883476483184405f;  // 1/sqrt(128)
#pragma unroll
    for (int i = 0; i < 4; i++) {
        float4 o = make_float4(acc[i][0] * scale, acc[i][1] * scale,
                               acc[i][2] * scale, acc[i][3] * scale);
        *(float4*)(out + (size_t)(r0 + i) * Sm + c0) = o;
    }
}

// attn[i, h*128 + d] = sum_j p[h,i,j] * v[j, (h/4)*128 + d]   (NN)
__global__ void pv_kernel(const float* __restrict__ p, const float* __restrict__ v,
                          float* __restrict__ attn) {
    int h = blockIdx.z;
    __shared__ float As[64][20];
    __shared__ float Bs[16][68];
    int tid = threadIdx.x;
    const float* Ab = p + (size_t)h * Sm * Sm + (size_t)blockIdx.y * 64 * Sm;
    const float* Bb = v + (h >> 2) * DHn + blockIdx.x * 64;
    int a_m = tid >> 2, a_k = (tid & 3) * 4;
    int bk = (tid * 4) >> 6, bn = (tid * 4) & 63;
    float acc[4][4] = {};
    for (int k0 = 0; k0 < Sm; k0 += 16) {
        *(float4*)(&As[a_m][a_k]) = *(const float4*)(Ab + (size_t)a_m * Sm + k0 + a_k);
        *(float4*)(&Bs[bk][bn])   = *(const float4*)(Bb + (size_t)(k0 + bk) * (HKVn * DHn) + bn);
        __syncthreads();
        mm_accum(As, Bs, acc, tid & 15, tid >> 4);
        __syncthreads();
    }
    int tx = tid & 15, ty = tid >> 4;
    int r0 = blockIdx.y * 64 + ty * 4;
    int c0 = h * DHn + blockIdx.x * 64 + tx * 4;
#pragma unroll
    for (int i = 0; i < 4; i++) {
        float4 o = make_float4(acc[i][0], acc[i][1], acc[i][2], acc[i][3]);
        *(float4*)(attn + (size_t)(r0 + i) * Dm + c0) = o;
    }
}

// Grouped expert GEMM: rows gathered via g_list[e], optional per-row scale (router score)
// C[t, n] = sum_k (scale_t * A[t, k]) * Ball[e, k, n]       K = 2048, ldb = 2048
__global__ void expert_gemm_kernel(const float* __restrict__ A,
                                   const float* __restrict__ Ball,
                                   float* __restrict__ C,
                                   const float* __restrict__ rowscale) {
    int e = blockIdx.z;
    int count = g_cnt[e];
    int row0 = blockIdx.y * 64;
    if (row0 >= count) return;
    __shared__ float As[64][20];
    __shared__ float Bs[16][68];
    __shared__ int   toks[64];
    __shared__ float scl[64];
    int tid = threadIdx.x;
    if (tid < 64) {
        int r = row0 + tid;
        int t = (r < count) ? g_list[e * Sm + r] : -1;
        toks[tid] = t;
        scl[tid] = (t >= 0) ? (rowscale ? rowscale[t] : 1.0f) : 0.0f;
    }
    __syncthreads();
    const float* Bb = Ball + (size_t)e * Dm * Fn + blockIdx.x * 64;
    int a_m = tid >> 2, a_k = (tid & 3) * 4;
    int bk = (tid * 4) >> 6, bn = (tid * 4) & 63;
    int tA = toks[a_m];
    float sA = scl[a_m];
    float acc[4][4] = {};
    for (int k0 = 0; k0 < Dm; k0 += 16) {
        float4 v = make_float4(0.f, 0.f, 0.f, 0.f);
        if (tA >= 0) v = *(const float4*)(A + (size_t)tA * Dm + k0 + a_k);
        v.x *= sA; v.y *= sA; v.z *= sA; v.w *= sA;
        *(float4*)(&As[a_m][a_k]) = v;
        *(float4*)(&Bs[bk][bn]) = *(const float4*)(Bb + (size_t)(k0 + bk) * Fn + bn);
        __syncthreads();
        mm_accum(As, Bs, acc, tid & 15, tid >> 4);
        __syncthreads();
    }
    int tx = tid & 15, ty = tid >> 4;
    int c0 = blockIdx.x * 64 + tx * 4;
#pragma unroll
    for (int i = 0; i < 4; i++) {
        int t = toks[ty * 4 + i];
        if (t >= 0) {
            float4 o = make_float4(acc[i][0], acc[i][1], acc[i][2], acc[i][3]);
            *(float4*)(C + (size_t)t * Fn + c0) = o;
        }
    }
}

// ---------------- launch ----------------
extern "C" void kernel_launch(void* const* d_in, const int* in_sizes, int n_in,
                              void* d_out, int out_size) {
    const float* hidden     = (const float*)d_in[0];
    const int*   amask      = (const int*)  d_in[1];
    const int*   pos        = (const int*)  d_in[2];
    const float* attn_nw    = (const float*)d_in[3];
    const float* wq         = (const float*)d_in[4];
    const float* wk         = (const float*)d_in[5];
    const float* wv         = (const float*)d_in[6];
    const float* wo         = (const float*)d_in[7];
    const float* ffn_nw     = (const float*)d_in[8];
    const float* router_w   = (const float*)d_in[9];
    const float* w_gate     = (const float*)d_in[10];
    const float* w_up       = (const float*)d_in[11];
    const float* w_down     = (const float*)d_in[12];
    const float* ws_gate    = (const float*)d_in[13];
    const float* ws_up      = (const float*)d_in[14];
    const float* ws_down    = (const float*)d_in[15];
    float* out = (float*)d_out;

    float *px, *pq, *pk, *pv, *psc, *pattn, *ph, *px2, *pts;
    float *peg, *peu, *pact, *prouted, *pgs, *pus, *psact, *pshared;
    int *pti;
    cudaGetSymbolAddress((void**)&px,      g_x);
    cudaGetSymbolAddress((void**)&pq,      g_q);
    cudaGetSymbolAddress((void**)&pk,      g_k);
    cudaGetSymbolAddress((void**)&pv,      g_v);
    cudaGetSymbolAddress((void**)&psc,     g_scores);
    cudaGetSymbolAddress((void**)&pattn,   g_attn);
    cudaGetSymbolAddress((void**)&ph,      g_h);
    cudaGetSymbolAddress((void**)&px2,     g_x2);
    cudaGetSymbolAddress((void**)&pti,     g_topidx);
    cudaGetSymbolAddress((void**)&pts,     g_topscore);
    cudaGetSymbolAddress((void**)&peg,     g_eg);
    cudaGetSymbolAddress((void**)&peu,     g_eu);
    cudaGetSymbolAddress((void**)&pact,    g_act);
    cudaGetSymbolAddress((void**)&prouted, g_routed);
    cudaGetSymbolAddress((void**)&pgs,     g_gs);
    cudaGetSymbolAddress((void**)&pus,     g_us);
    cudaGetSymbolAddress((void**)&psact,   g_sact);
    cudaGetSymbolAddress((void**)&pshared, g_shared);

    // --- attention block ---
    rmsnorm_kernel<<<Sm, 256>>>(hidden, attn_nw, px);
    sgemm_nn_kernel<<<dim3(32, 8), 256>>>(px, Dm, wq, Dm, pq, Dm, Dm, nullptr);
    sgemm_nn_kernel<<<dim3(8, 8),  256>>>(px, Dm, wk, 512, pk, 512, Dm, nullptr);
    sgemm_nn_kernel<<<dim3(8, 8),  256>>>(px, Dm, wv, 512, pv, 512, Dm, nullptr);
    rope_kernel<<<Sm, 256>>>(pq, pk, pos);
    scores_kernel<<<dim3(8, 8, Hn), 256>>>(pq, pk, psc);
    softmax_kernel<<<dim3(Sm, Hn), 256>>>(psc, amask);
    pv_kernel<<<dim3(2, 8, Hn), 256>>>(psc, pv, pattn);
    sgemm_nn_kernel<<<dim3(32, 8), 256>>>(pattn, Dm, wo, Dm, ph, Dm, Dm, hidden);

    // --- MoE block ---
    rmsnorm_kernel<<<Sm, 256>>>(ph, ffn_nw, px2);
    router_kernel<<<Sm, 256>>>(px2, router_w, pti, pts);
    dispatch_kernel<<<1, Sm>>>(pti);
    expert_gemm_kernel<<<dim3(32, 8, En), 256>>>(px2, w_gate, peg, pts);
    expert_gemm_kernel<<<dim3(32, 8, En), 256>>>(px2, w_up,   peu, pts);
    silumul_kernel<<<(Sm * Fn) / 256, 256>>>(peg, peu, pact, Sm * Fn);
    expert_gemm_kernel<<<dim3(32, 8, En), 256>>>(pact, w_down, prouted, nullptr);

    // shared expert
    sgemm_nn_kernel<<<dim3(32, 8), 256>>>(px2, Dm, ws_gate, Fn, pgs, Fn, Dm, nullptr);
    sgemm_nn_kernel<<<dim3(32, 8), 256>>>(px2, Dm, ws_up,   Fn, pus, Fn, Dm, nullptr);
    silumul_kernel<<<(Sm * Fn) / 256, 256>>>(pgs, pus, psact, Sm * Fn);
    sgemm_nn_kernel<<<dim3(32, 8), 256>>>(psact, Fn, ws_down, Dm, pshared, Dm, Fn, nullptr);

    // final: out = h + routed + shared
    add3_kernel<<<(Sm * Dm) / 256, 256>>>(ph, prouted, pshared, out);
}

// round 2
// speedup vs baseline: 1.0043x; 1.0043x over previous
#include <cuda_runtime.h>
#include <math.h>

#define Dm   2048
#define Sm   512
#define Hn   16
#define HKVn 4
#define DHn  128
#define Fn   2048
#define En   8

// ---------------- scratch (device globals; no allocation allowed) ----------------
__device__ float g_x[Sm*Dm];
__device__ float g_q[Sm*Dm];
__device__ float g_k[Sm*HKVn*DHn];
__device__ float g_v[Sm*HKVn*DHn];
__device__ float g_scores[Hn*Sm*Sm];
__device__ float g_attn[Sm*Dm];
__device__ float g_h[Sm*Dm];
__device__ float g_x2[Sm*Dm];
__device__ int   g_topidx[Sm];
__device__ float g_topscore[Sm];
__device__ int   g_cnt[En];
__device__ int   g_list[En*Sm];
__device__ float g_eg[Sm*Fn];
__device__ float g_eu[Sm*Fn];
__device__ float g_act[Sm*Fn];
__device__ float g_routed[Sm*Dm];
__device__ float g_gs[Sm*Fn];
__device__ float g_us[Sm*Fn];
__device__ float g_sact[Sm*Fn];
__device__ float g_shared[Sm*Dm];

// ---------------- small kernels ----------------
__global__ void rmsnorm_kernel(const float* __restrict__ in, const float* __restrict__ w,
                               float* __restrict__ out) {
    int t = blockIdx.x;
    const float* row = in + (size_t)t * Dm;
    float s = 0.f;
    for (int d = threadIdx.x; d < Dm; d += 256) { float v = row[d]; s += v * v; }
    __shared__ float red[256];
    red[threadIdx.x] = s; __syncthreads();
    for (int off = 128; off > 0; off >>= 1) {
        if (threadIdx.x < off) red[threadIdx.x] += red[threadIdx.x + off];
        __syncthreads();
    }
    float r = rsqrtf(red[0] / (float)Dm + 1e-5f);
    for (int d = threadIdx.x; d < Dm; d += 256)
        out[(size_t)t * Dm + d] = row[d] * r * w[d];
}

__global__ void rope_kernel(float* __restrict__ q, float* __restrict__ k,
                            const int* __restrict__ pos_ids) {
    int t = blockIdx.x;
    float p = (float)pos_ids[t];
    for (int idx = threadIdx.x; idx < (Hn + HKVn) * 64; idx += blockDim.x) {
        int head = idx >> 6;
        int i = idx & 63;
        float inv = powf(500000.0f, -(float)i / 64.0f);
        float f = p * inv;
        float sn, cs;
        sincosf(f, &sn, &cs);
        float* base;
        if (head < Hn) base = q + (size_t)t * Dm + head * DHn;
        else           base = k + (size_t)t * (HKVn * DHn) + (head - Hn) * DHn;
        float x1 = base[i], x2 = base[i + 64];
        base[i]      = x1 * cs - x2 * sn;
        base[i + 64] = x2 * cs + x1 * sn;
    }
}

__global__ void softmax_kernel(float* __restrict__ sc, const int* __restrict__ mask) {
    int i = blockIdx.x;   // query
    int h = blockIdx.y;   // head
    float* row = sc + ((size_t)h * Sm + i) * Sm;
    int tid = threadIdx.x;
    int j0 = tid, j1 = tid + 256;
    float s0 = (j0 <= i && mask[j0] > 0) ? row[j0] : -1e9f;
    float s1 = (j1 <= i && mask[j1] > 0) ? row[j1] : -1e9f;
    __shared__ float red[256];
    red[tid] = fmaxf(s0, s1); __syncthreads();
    for (int off = 128; off > 0; off >>= 1) {
        if (tid < off) red[tid] = fmaxf(red[tid], red[tid + off]);
        __syncthreads();
    }
    float m = red[0];
    __syncthreads();
    float e0 = expf(s0 - m), e1 = expf(s1 - m);
    red[tid] = e0 + e1; __syncthreads();
    for (int off = 128; off > 0; off >>= 1) {
        if (tid < off) red[tid] += red[tid + off];
        __syncthreads();
    }
    float inv = 1.f / red[0];
    row[j0] = e0 * inv;
    row[j1] = e1 * inv;
}

__global__ void router_kernel(const float* __restrict__ x2, const float* __restrict__ rw,
                              int* __restrict__ topidx, float* __restrict__ topscore) {
    int t = blockIdx.x;
    int w = threadIdx.x >> 5, lane = threadIdx.x & 31;
    float s = 0.f;
    for (int d = lane; d < Dm; d += 32)
        s += x2[(size_t)t * Dm + d] * rw[d * En + w];
    for (int off = 16; off; off >>= 1) s += __shfl_down_sync(0xffffffff, s, off);
    __shared__ float logits[En];
    if (lane == 0) logits[w] = s;
    __syncthreads();
    if (threadIdx.x == 0) {
        int best = 0; float bv = logits[0];
        for (int e = 1; e < En; e++) if (logits[e] > bv) { bv = logits[e]; best = e; }
        topidx[t] = best;
        topscore[t] = 1.f / (1.f + expf(-bv));
    }
}

__global__ void dispatch_kernel(const int* __restrict__ topidx) {
    int t = threadIdx.x;  // 512 threads
    if (t < En) g_cnt[t] = 0;
    __syncthreads();
    int e = topidx[t];
    int pos = atomicAdd(&g_cnt[e], 1);
    g_list[e * Sm + pos] = t;
}

__global__ void silumul_kernel(const float* __restrict__ g, const float* __restrict__ u,
                               float* __restrict__ out, int n) {
    int i = blockIdx.x * 256 + threadIdx.x;
    if (i < n) {
        float x = g[i];
        out[i] = (x / (1.f + expf(-x))) * u[i];
    }
}

__global__ void add3_kernel(const float* __restrict__ a, const float* __restrict__ b,
                            const float* __restrict__ c, float* __restrict__ out) {
    int i = blockIdx.x * 256 + threadIdx.x;
    out[i] = a[i] + b[i] + c[i];
}

// ---------------- GEMM tile machinery (64x64x16, 4x4/thread, 256 threads) -------
__device__ __forceinline__ void mm_accum(const float (*As)[20], const float (*Bs)[68],
                                         float acc[4][4], int tx, int ty) {
#pragma unroll
    for (int kk = 0; kk < 16; kk++) {
        float a[4];
#pragma unroll
        for (int i = 0; i < 4; i++) a[i] = As[ty * 4 + i][kk];
        float4 b = *(const float4*)(&Bs[kk][tx * 4]);
#pragma unroll
        for (int i = 0; i < 4; i++) {
            acc[i][0] += a[i] * b.x;
            acc[i][1] += a[i] * b.y;
            acc[i][2] += a[i] * b.z;
            acc[i][3] += a[i] * b.w;
        }
    }
}

// C[m,n] = sum_k A[m,k]*B[k,n]  (+ res[m,n]); tile fully in-bounds (all dims %64==0)
__global__ void sgemm_nn_kernel(const float* __restrict__ A, int lda,
                                const float* __restrict__ B, int ldb,
                                float* __restrict__ C, int ldc, int K,
                                const float* __restrict__ res) {
    __shared__ float As[64][20];
    __shared__ float Bs[16][68];
    int tid = threadIdx.x;
    const float* Ab = A + (size_t)blockIdx.y * 64 * lda;
    const float* Bb = B + blockIdx.x * 64;
    int a_m = tid >> 2, a_k = (tid & 3) * 4;
    int bk = (tid * 4) >> 6, bn = (tid * 4) & 63;
    float acc[4][4] = {};
    for (int k0 = 0; k0 < K; k0 += 16) {
        *(float4*)(&As[a_m][a_k]) = *(const float4*)(Ab + (size_t)a_m * lda + k0 + a_k);
        *(float4*)(&Bs[bk][bn])   = *(const float4*)(Bb + (size_t)(k0 + bk) * ldb + bn);
        __syncthreads();
        mm_accum(As, Bs, acc, tid & 15, tid >> 4);
        __syncthreads();
    }
    int tx = tid & 15, ty = tid >> 4;
    int r0 = blockIdx.y * 64 + ty * 4, c0 = blockIdx.x * 64 + tx * 4;
#pragma unroll
    for (int i = 0; i < 4; i++) {
        float4 o = make_float4(acc[i][0], acc[i][1], acc[i][2], acc[i][3]);
        if (res) {
            const float4 rv = *(const float4*)(res + (size_t)(r0 + i) * ldc + c0);
            o.x += rv.x; o.y += rv.y; o.z += rv.z; o.w += rv.w;
        }
        *(float4*)(C + (size_t)(r0 + i) * ldc + c0) = o;
    }
}

// scores[h,i,j] = (1/sqrt(128)) * sum_d q[i, h*128+d] * k[j, (h/4)*128+d]   (NT)
__global__ void scores_kernel(const float* __restrict__ q, const float* __restrict__ k,
                              float* __restrict__ sc) {
    int h = blockIdx.z;
    __shared__ float As[64][20];
    __shared__ float Bs[16][68];
    int tid = threadIdx.x;
    const float* Ab = q + (size_t)blockIdx.y * 64 * Dm + h * DHn;
    const float* Bb = k + (size_t)blockIdx.x * 64 * (HKVn * DHn) + (h >> 2) * DHn;
    int a_m = tid >> 2, a_k = (tid & 3) * 4;
    int bn = tid >> 2, bkk = (tid & 3) * 4;
    float acc[4][4] = {};
    for (int k0 = 0; k0 < DHn; k0 += 16) {
        *(float4*)(&As[a_m][a_k]) = *(const float4*)(Ab + (size_t)a_m * Dm + k0 + a_k);
        float4 bv = *(const float4*)(Bb + (size_t)bn * (HKVn * DHn) + k0 + bkk);
        Bs[bkk + 0][bn] = bv.x; Bs[bkk + 1][bn] = bv.y;
        Bs[bkk + 2][bn] = bv.z; Bs[bkk + 3][bn] = bv.w;
        __syncthreads();
        mm_accum(As, Bs, acc, tid & 15, tid >> 4);
        __syncthreads();
    }
    int tx = tid & 15, ty = tid >> 4;
    float* out = sc + (size_t)h * Sm * Sm;
    int r0 = blockIdx.y * 64 + ty * 4, c0 = blockIdx.x * 64 + tx * 4;
    const float scale = 0.0883883476483184405f;  // 1/sqrt(128)
#pragma unroll
    for (int i = 0; i < 4; i++) {
        float4 o = make_float4(acc[i][0] * scale, acc[i][1] * scale,
                               acc[i][2] * scale, acc[i][3] * scale);
        *(float4*)(out + (size_t)(r0 + i) * Sm + c0) = o;
    }
}

// attn[i, h*128 + d] = sum_j p[h,i,j] * v[j, (h/4)*128 + d]   (NN)
__global__ void pv_kernel(const float* __restrict__ p, const float* __restrict__ v,
                          float* __restrict__ attn) {
    int h = blockIdx.z;
    __shared__ float As[64][20];
    __shared__ float Bs[16][68];
    int tid = threadIdx.x;
    const float* Ab = p + (size_t)h * Sm * Sm + (size_t)blockIdx.y * 64 * Sm;
    const float* Bb = v + (h >> 2) * DHn + blockIdx.x * 64;
    int a_m = tid >> 2, a_k = (tid & 3) * 4;
    int bk = (tid * 4) >> 6, bn = (tid * 4) & 63;
    float acc[4][4] = {};
    for (int k0 = 0; k0 < Sm; k0 += 16) {
        *(float4*)(&As[a_m][a_k]) = *(const float4*)(Ab + (size_t)a_m * Sm + k0 + a_k);
        *(float4*)(&Bs[bk][bn])   = *(const float4*)(Bb + (size_t)(k0 + bk) * (HKVn * DHn) + bn);
        __syncthreads();
        mm_accum(As, Bs, acc, tid & 15, tid >> 4);
        __syncthreads();
    }
    int tx = tid & 15, ty = tid >> 4;
    int r0 = blockIdx.y * 64 + ty * 4;
    int c0 = h * DHn + blockIdx.x * 64 + tx * 4;
#pragma unroll
    for (int i = 0; i < 4; i++) {
        float4 o = make_float4(acc[i][0], acc[i][1], acc[i][2], acc[i][3]);
        *(float4*)(attn + (size_t)(r0 + i) * Dm + c0) = o;
    }
}

// Grouped expert GEMM: rows gathered via g_list[e], optional per-row scale (router score)
// C[t, n] = sum_k (scale_t * A[t, k]) * Ball[e, k, n]       K = 2048, ldb = 2048
__global__ void expert_gemm_kernel(const float* __restrict__ A,
                                   const float* __restrict__ Ball,
                                   float* __restrict__ C,
                                   const float* __restrict__ rowscale) {
    int e = blockIdx.z;
    int count = g_cnt[e];
    int row0 = blockIdx.y * 64;
    if (row0 >= count) return;
    __shared__ float As[64][20];
    __shared__ float Bs[16][68];
    __shared__ int   toks[64];
    __shared__ float scl[64];
    int tid = threadIdx.x;
    if (tid < 64) {
        int r = row0 + tid;
        int t = (r < count) ? g_list[e * Sm + r] : -1;
        toks[tid] = t;
        scl[tid] = (t >= 0) ? (rowscale ? rowscale[t] : 1.0f) : 0.0f;
    }
    __syncthreads();
    const float* Bb = Ball + (size_t)e * Dm * Fn + blockIdx.x * 64;
    int a_m = tid >> 2, a_k = (tid & 3) * 4;
    int bk = (tid * 4) >> 6, bn = (tid * 4) & 63;
    int tA = toks[a_m];
    float sA = scl[a_m];
    float acc[4][4] = {};
    for (int k0 = 0; k0 < Dm; k0 += 16) {
        float4 v = make_float4(0.f, 0.f, 0.f, 0.f);
        if (tA >= 0) v = *(const float4*)(A + (size_t)tA * Dm + k0 + a_k);
        v.x *= sA; v.y *= sA; v.z *= sA; v.w *= sA;
        *(float4*)(&As[a_m][a_k]) = v;
        *(float4*)(&Bs[bk][bn]) = *(const float4*)(Bb + (size_t)(k0 + bk) * Fn + bn);
        __syncthreads();
        mm_accum(As, Bs, acc, tid & 15, tid >> 4);
        __syncthreads();
    }
    int tx = tid & 15, ty = tid >> 4;
    int c0 = blockIdx.x * 64 + tx * 4;
#pragma unroll
    for (int i = 0; i < 4; i++) {
        int t = toks[ty * 4 + i];
        if (t >= 0) {
            float4 o = make_float4(acc[i][0], acc[i][1], acc[i][2], acc[i][3]);
            *(float4*)(C + (size_t)t * Fn + c0) = o;
        }
    }
}

// ---------------- launch ----------------
extern "C" void kernel_launch(void* const* d_in, const int* in_sizes, int n_in,
                              void* d_out, int out_size) {
    const float* hidden     = (const float*)d_in[0];
    const int*   amask      = (const int*)  d_in[1];
    const int*   pos        = (const int*)  d_in[2];
    const float* attn_nw    = (const float*)d_in[3];
    const float* wq         = (const float*)d_in[4];
    const float* wk         = (const float*)d_in[5];
    const float* wv         = (const float*)d_in[6];
    const float* wo         = (const float*)d_in[7];
    const float* ffn_nw     = (const float*)d_in[8];
    const float* router_w   = (const float*)d_in[9];
    const float* w_gate     = (const float*)d_in[10];
    const float* w_up       = (const float*)d_in[11];
    const float* w_down     = (const float*)d_in[12];
    const float* ws_gate    = (const float*)d_in[13];
    const float* ws_up      = (const float*)d_in[14];
    const float* ws_down    = (const float*)d_in[15];
    float* out = (float*)d_out;

    float *px, *pq, *pk, *pv, *psc, *pattn, *ph, *px2, *pts;
    float *peg, *peu, *pact, *prouted, *pgs, *pus, *psact, *pshared;
    int *pti;
    cudaGetSymbolAddress((void**)&px,      g_x);
    cudaGetSymbolAddress((void**)&pq,      g_q);
    cudaGetSymbolAddress((void**)&pk,      g_k);
    cudaGetSymbolAddress((void**)&pv,      g_v);
    cudaGetSymbolAddress((void**)&psc,     g_scores);
    cudaGetSymbolAddress((void**)&pattn,   g_attn);
    cudaGetSymbolAddress((void**)&ph,      g_h);
    cudaGetSymbolAddress((void**)&px2,     g_x2);
    cudaGetSymbolAddress((void**)&pti,     g_topidx);
    cudaGetSymbolAddress((void**)&pts,     g_topscore);
    cudaGetSymbolAddress((void**)&peg,     g_eg);
    cudaGetSymbolAddress((void**)&peu,     g_eu);
    cudaGetSymbolAddress((void**)&pact,    g_act);
    cudaGetSymbolAddress((void**)&prouted, g_routed);
    cudaGetSymbolAddress((void**)&pgs,     g_gs);
    cudaGetSymbolAddress((void**)&pus,     g_us);
    cudaGetSymbolAddress((void**)&psact,   g_sact);
    cudaGetSymbolAddress((void**)&pshared, g_shared);

    // --- attention block ---
    rmsnorm_kernel<<<Sm, 256>>>(hidden, attn_nw, px);
    sgemm_nn_kernel<<<dim3(32, 8), 256>>>(px, Dm, wq, Dm, pq, Dm, Dm, nullptr);
    sgemm_nn_kernel<<<dim3(8, 8),  256>>>(px, Dm, wk, 512, pk, 512, Dm, nullptr);
    sgemm_nn_kernel<<<dim3(8, 8),  256>>>(px, Dm, wv, 512, pv, 512, Dm, nullptr);
    rope_kernel<<<Sm, 256>>>(pq, pk, pos);
    scores_kernel<<<dim3(8, 8, Hn), 256>>>(pq, pk, psc);
    softmax_kernel<<<dim3(Sm, Hn), 256>>>(psc, amask);
    pv_kernel<<<dim3(2, 8, Hn), 256>>>(psc, pv, pattn);
    sgemm_nn_kernel<<<dim3(32, 8), 256>>>(pattn, Dm, wo, Dm, ph, Dm, Dm, hidden);

    // --- MoE block ---
    rmsnorm_kernel<<<Sm, 256>>>(ph, ffn_nw, px2);
    router_kernel<<<Sm, 256>>>(px2, router_w, pti, pts);
    dispatch_kernel<<<1, Sm>>>(pti);
    expert_gemm_kernel<<<dim3(32, 8, En), 256>>>(px2, w_gate, peg, pts);
    expert_gemm_kernel<<<dim3(32, 8, En), 256>>>(px2, w_up,   peu, pts);
    silumul_kernel<<<(Sm * Fn) / 256, 256>>>(peg, peu, pact, Sm * Fn);
    expert_gemm_kernel<<<dim3(32, 8, En), 256>>>(pact, w_down, prouted, nullptr);

    // shared expert
    sgemm_nn_kernel<<<dim3(32, 8), 256>>>(px2, Dm, ws_gate, Fn, pgs, Fn, Dm, nullptr);
    sgemm_nn_kernel<<<dim3(32, 8), 256>>>(px2, Dm, ws_up,   Fn, pus, Fn, Dm, nullptr);
    silumul_kernel<<<(Sm * Fn) / 256, 256>>>(pgs, pus, psact, Sm * Fn);
    sgemm_nn_kernel<<<dim3(32, 8), 256>>>(psact, Fn, ws_down, Dm, pshared, Dm, Fn, nullptr);

    // final: out = h + routed + shared
    add3_kernel<<<(Sm * Dm) / 256, 256>>>(ph, prouted, pshared, out);
}

// round 4
// speedup vs baseline: 1.1053x; 1.1006x over previous
#include <cuda_runtime.h>
#include <cuda_bf16.h>
#include <stdint.h>
#include <math.h>

#define Dm   2048
#define Sm   512
#define Hn   16
#define HKVn 4
#define DHn  128
#define Fn   2048
#define En   8

// ---------------- scratch (device globals; no allocation allowed) ----------------
__device__ float g_x[Sm*Dm];
__device__ float g_q[Sm*Dm];
__device__ float g_k[Sm*HKVn*DHn];
__device__ float g_v[Sm*HKVn*DHn];
__device__ float g_scores[Hn*Sm*Sm];
__device__ float g_attn[Sm*Dm];
__device__ float g_h[Sm*Dm];
__device__ float g_x2[Sm*Dm];
__device__ int   g_topidx[Sm];
__device__ float g_topscore[Sm];
__device__ int   g_cnt[En];
__device__ int   g_list[En*Sm];
__device__ float g_eg[Sm*Fn];
__device__ float g_eu[Sm*Fn];
__device__ float g_act[Sm*Fn];
__device__ float g_routed[Sm*Dm];
__device__ float g_gs[Sm*Fn];
__device__ float g_us[Sm*Fn];
__device__ float g_sact[Sm*Fn];
__device__ float g_shared[Sm*Dm];

// a -> low half (even k), b -> high half (odd k)
__device__ __forceinline__ uint32_t pack_bf16x2(float a, float b) {
    uint32_t r;
    asm("cvt.rn.bf16x2.f32 %0, %1, %2;" : "=r"(r) : "f"(b), "f"(a));
    return r;
}

__device__ __forceinline__ void mma16816(float c[4], const uint32_t a[4], const uint32_t b[2]) {
    asm volatile(
        "mma.sync.aligned.m16n8k16.row.col.f32.bf16.bf16.f32 "
        "{%0,%1,%2,%3}, {%4,%5,%6,%7}, {%8,%9}, {%0,%1,%2,%3};"
        : "+f"(c[0]), "+f"(c[1]), "+f"(c[2]), "+f"(c[3])
        : "r"(a[0]), "r"(a[1]), "r"(a[2]), "r"(a[3]), "r"(b[0]), "r"(b[1]));
}

// =============== bf16 split-precision HMMA GEMM (128x128 tile, K=2048) ===============
// C[t,n] = sum_k (scale_t * A[t,k]) * B[k,n]  (+ res[t,n])
// gather=1: e=blockIdx.z, rows via g_list[e], B += e*2048*ldb
#define AW 40      // A smem row pitch in u32 words (32 data + 8 pad)
#define BW 136     // B smem row pitch in u32 words (128 data + 8 pad)
#define ASZ (128*AW)           // 5120 words
#define STAGE_W (2*ASZ + 2*32*BW)  // 10240 + 8704 = 18944 words
#define HG_SMEM (2*STAGE_W*4)      // 151552 bytes

__global__ void __launch_bounds__(256, 1) hgemm_kernel(
    const float* __restrict__ A, int lda,
    const float* __restrict__ B, int ldb,
    float* __restrict__ C, int ldc,
    const float* __restrict__ res,
    const float* __restrict__ rowscale,
    int M, int gather)
{
    extern __shared__ uint32_t smw[];
    __shared__ int   tok[128];
    __shared__ float scl[128];

    int row0 = blockIdx.y * 128;
    int n0   = blockIdx.x * 128;
    int tid  = threadIdx.x;

    if (gather) {
        int e = blockIdx.z;
        int count = g_cnt[e];
        if (row0 >= count) return;
        B += (size_t)e * 2048 * ldb;
        if (tid < 128) {
            int r = row0 + tid;
            int t = (r < count) ? g_list[e * Sm + r] : -1;
            tok[tid] = t;
            scl[tid] = (t >= 0 && rowscale) ? rowscale[t] : 1.0f;
        }
    } else {
        if (tid < 128) { tok[tid] = row0 + tid; scl[tid] = 1.0f; }
    }
    __syncthreads();

    int lane = tid & 31, wid = tid >> 5;
    int gr = lane >> 2, tg = lane & 3;
    int wm = wid >> 2, wn = wid & 3;   // 2 x 4 warp grid

    float acc[4][4][4];
#pragma unroll
    for (int i = 0; i < 4; i++)
#pragma unroll
        for (int j = 0; j < 4; j++)
#pragma unroll
            for (int r = 0; r < 4; r++) acc[i][j][r] = 0.f;

    for (int st = 0; st < 32; st++) {
        uint32_t* buf = smw + (st & 1) * STAGE_W;
        uint32_t* AH = buf;
        uint32_t* AL = buf + ASZ;
        uint32_t* BH = buf + 2 * ASZ;
        uint32_t* BL = BH + 32 * BW;
        int k0 = st * 64;

        // ---- stage A (128 rows x 64 k) as bf16 hi/lo pairs ----
#pragma unroll
        for (int it = 0; it < 8; it++) {
            int linear = it * 256 + tid;
            int m = linear >> 4, c4 = linear & 15;
            int t = tok[m];
            float4 v = make_float4(0.f, 0.f, 0.f, 0.f);
            if (t >= 0) v = *(const float4*)(A + (size_t)t * lda + k0 + c4 * 4);
            float s = scl[m];
            v.x *= s; v.y *= s; v.z *= s; v.w *= s;
            uint32_t h01 = pack_bf16x2(v.x, v.y);
            uint32_t h23 = pack_bf16x2(v.z, v.w);
            float hx = __uint_as_float(h01 << 16);
            float hy = __uint_as_float(h01 & 0xffff0000u);
            float hz = __uint_as_float(h23 << 16);
            float hw = __uint_as_float(h23 & 0xffff0000u);
            uint32_t l01 = pack_bf16x2(v.x - hx, v.y - hy);
            uint32_t l23 = pack_bf16x2(v.z - hz, v.w - hw);
            int w = m * AW + c4 * 2;
            AH[w] = h01; AH[w + 1] = h23;
            AL[w] = l01; AL[w + 1] = l23;
        }
        // ---- stage B (64 k x 128 n), k-pairs packed per word ----
#pragma unroll
        for (int it = 0; it < 8; it++) {
            int linear = it * 256 + tid;
            int n = linear & 127, kg = linear >> 7;   // kg in 0..15 (4 k each)
            const float* bp = B + (size_t)(k0 + kg * 4) * ldb + n0 + n;
            float f0 = bp[0];
            float f1 = bp[(size_t)ldb];
            float f2 = bp[2 * (size_t)ldb];
            float f3 = bp[3 * (size_t)ldb];
            uint32_t h01 = pack_bf16x2(f0, f1);
            uint32_t h23 = pack_bf16x2(f2, f3);
            float hx = __uint_as_float(h01 << 16);
            float hy = __uint_as_float(h01 & 0xffff0000u);
            float hz = __uint_as_float(h23 << 16);
            float hw = __uint_as_float(h23 & 0xffff0000u);
            uint32_t l01 = pack_bf16x2(f0 - hx, f1 - hy);
            uint32_t l23 = pack_bf16x2(f2 - hz, f3 - hw);
            int w0 = (kg * 2) * BW + n;
            BH[w0] = h01; BH[w0 + BW] = h23;
            BL[w0] = l01; BL[w0 + BW] = l23;
        }
        __syncthreads();

        // ---- 4 k16 steps of mma ----
#pragma unroll
        for (int ks = 0; ks < 4; ks++) {
            uint32_t aH[4][4], aL[4][4], bH[4][2], bL[4][2];
#pragma unroll
            for (int mt = 0; mt < 4; mt++) {
                int r = wm * 64 + mt * 16 + gr;
                int w0 = r * AW + ks * 8 + tg;
                aH[mt][0] = AH[w0];           aH[mt][1] = AH[w0 + 8 * AW];
                aH[mt][2] = AH[w0 + 4];       aH[mt][3] = AH[w0 + 8 * AW + 4];
                aL[mt][0] = AL[w0];           aL[mt][1] = AL[w0 + 8 * AW];
                aL[mt][2] = AL[w0 + 4];       aL[mt][3] = AL[w0 + 8 * AW + 4];
            }
#pragma unroll
            for (int nt = 0; nt < 4; nt++) {
                int c = wn * 32 + nt * 8 + gr;
                int w0 = (ks * 8 + tg) * BW + c;
                bH[nt][0] = BH[w0]; bH[nt][1] = BH[w0 + 4 * BW];
                bL[nt][0] = BL[w0]; bL[nt][1] = BL[w0 + 4 * BW];
            }
#pragma unroll
            for (int mt = 0; mt < 4; mt++)
#pragma unroll
                for (int nt = 0; nt < 4; nt++) {
                    mma16816(acc[mt][nt], aH[mt], bH[nt]);
                    mma16816(acc[mt][nt], aH[mt], bL[nt]);
                    mma16816(acc[mt][nt], aL[mt], bH[nt]);
                }
        }
        __syncthreads();
    }

    // ---- epilogue ----
#pragma unroll
    for (int mt = 0; mt < 4; mt++) {
        int r1 = wm * 64 + mt * 16 + gr;
        int r2 = r1 + 8;
        int t1 = tok[r1], t2 = tok[r2];
#pragma unroll
        for (int nt = 0; nt < 4; nt++) {
            int col = n0 + wn * 32 + nt * 8 + tg * 2;
            if (t1 >= 0) {
                float2 o = make_float2(acc[mt][nt][0], acc[mt][nt][1]);
                if (res) {
                    float2 rv = *(const float2*)(res + (size_t)t1 * ldc + col);
                    o.x += rv.x; o.y += rv.y;
                }
                *(float2*)(C + (size_t)t1 * ldc + col) = o;
            }
            if (t2 >= 0) {
                float2 o = make_float2(acc[mt][nt][2], acc[mt][nt][3]);
                if (res) {
                    float2 rv = *(const float2*)(res + (size_t)t2 * ldc + col);
                    o.x += rv.x; o.y += rv.y;
                }
                *(float2*)(C + (size_t)t2 * ldc + col) = o;
            }
        }
    }
}

// ---------------- small kernels ----------------
__global__ void rmsnorm_kernel(const float* __restrict__ in, const float* __restrict__ w,
                               float* __restrict__ out) {
    int t = blockIdx.x;
    const float* row = in + (size_t)t * Dm;
    float s = 0.f;
    for (int d = threadIdx.x; d < Dm; d += 256) { float v = row[d]; s += v * v; }
    __shared__ float red[256];
    red[threadIdx.x] = s; __syncthreads();
    for (int off = 128; off > 0; off >>= 1) {
        if (threadIdx.x < off) red[threadIdx.x] += red[threadIdx.x + off];
        __syncthreads();
    }
    float r = rsqrtf(red[0] / (float)Dm + 1e-5f);
    for (int d = threadIdx.x; d < Dm; d += 256)
        out[(size_t)t * Dm + d] = row[d] * r * w[d];
}

__global__ void rope_kernel(float* __restrict__ q, float* __restrict__ k,
                            const int* __restrict__ pos_ids) {
    int t = blockIdx.x;
    float p = (float)pos_ids[t];
    for (int idx = threadIdx.x; idx < (Hn + HKVn) * 64; idx += blockDim.x) {
        int head = idx >> 6;
        int i = idx & 63;
        float inv = powf(500000.0f, -(float)i / 64.0f);
        float f = p * inv;
        float sn, cs;
        sincosf(f, &sn, &cs);
        float* base;
        if (head < Hn) base = q + (size_t)t * Dm + head * DHn;
        else           base = k + (size_t)t * (HKVn * DHn) + (head - Hn) * DHn;
        float x1 = base[i], x2 = base[i + 64];
        base[i]      = x1 * cs - x2 * sn;
        base[i + 64] = x2 * cs + x1 * sn;
    }
}

__global__ void softmax_kernel(float* __restrict__ sc, const int* __restrict__ mask) {
    int i = blockIdx.x;
    int h = blockIdx.y;
    float* row = sc + ((size_t)h * Sm + i) * Sm;
    int tid = threadIdx.x;
    int j0 = tid, j1 = tid + 256;
    float s0 = (j0 <= i && mask[j0] > 0) ? row[j0] : -1e9f;
    float s1 = (j1 <= i && mask[j1] > 0) ? row[j1] : -1e9f;
    __shared__ float red[256];
    red[tid] = fmaxf(s0, s1); __syncthreads();
    for (int off = 128; off > 0; off >>= 1) {
        if (tid < off) red[tid] = fmaxf(red[tid], red[tid + off]);
        __syncthreads();
    }
    float m = red[0];
    __syncthreads();
    float e0 = expf(s0 - m), e1 = expf(s1 - m);
    red[tid] = e0 + e1; __syncthreads();
    for (int off = 128; off > 0; off >>= 1) {
        if (tid < off) red[tid] += red[tid + off];
        __syncthreads();
    }
    float inv = 1.f / red[0];
    row[j0] = e0 * inv;
    row[j1] = e1 * inv;
}

__global__ void router_kernel(const float* __restrict__ x2, const float* __restrict__ rw,
                              int* __restrict__ topidx, float* __restrict__ topscore) {
    int t = blockIdx.x;
    int w = threadIdx.x >> 5, lane = threadIdx.x & 31;
    float s = 0.f;
    for (int d = lane; d < Dm; d += 32)
        s += x2[(size_t)t * Dm + d] * rw[d * En + w];
    for (int off = 16; off; off >>= 1) s += __shfl_down_sync(0xffffffff, s, off);
    __shared__ float logits[En];
    if (lane == 0) logits[w] = s;
    __syncthreads();
    if (threadIdx.x == 0) {
        int best = 0; float bv = logits[0];
        for (int e = 1; e < En; e++) if (logits[e] > bv) { bv = logits[e]; best = e; }
        topidx[t] = best;
        topscore[t] = 1.f / (1.f + expf(-bv));
    }
}

__global__ void dispatch_kernel(const int* __restrict__ topidx) {
    int t = threadIdx.x;
    if (t < En) g_cnt[t] = 0;
    __syncthreads();
    int e = topidx[t];
    int pos = atomicAdd(&g_cnt[e], 1);
    g_list[e * Sm + pos] = t;
}

__global__ void silumul_kernel(const float* __restrict__ g, const float* __restrict__ u,
                               float* __restrict__ out, int n) {
    int i = blockIdx.x * 256 + threadIdx.x;
    if (i < n) {
        float x = g[i];
        out[i] = (x / (1.f + expf(-x))) * u[i];
    }
}

__global__ void add3_kernel(const float* __restrict__ a, const float* __restrict__ b,
                            const float* __restrict__ c, float* __restrict__ out) {
    int i = blockIdx.x * 256 + threadIdx.x;
    out[i] = a[i] + b[i] + c[i];
}

// ---------------- fp32 attention tile machinery (scores / pv) ----------------
__device__ __forceinline__ void mm_accum(const float (*As)[20], const float (*Bs)[68],
                                         float acc[4][4], int tx, int ty) {
#pragma unroll
    for (int kk = 0; kk < 16; kk++) {
        float a[4];
#pragma unroll
        for (int i = 0; i < 4; i++) a[i] = As[ty * 4 + i][kk];
        float4 b = *(const float4*)(&Bs[kk][tx * 4]);
#pragma unroll
        for (int i = 0; i < 4; i++) {
            acc[i][0] += a[i] * b.x;
            acc[i][1] += a[i] * b.y;
            acc[i][2] += a[i] * b.z;
            acc[i][3] += a[i] * b.w;
        }
    }
}

__global__ void scores_kernel(const float* __restrict__ q, const float* __restrict__ k,
                              float* __restrict__ sc) {
    int h = blockIdx.z;
    __shared__ float As[64][20];
    __shared__ float Bs[16][68];
    int tid = threadIdx.x;
    const float* Ab = q + (size_t)blockIdx.y * 64 * Dm + h * DHn;
    const float* Bb = k + (size_t)blockIdx.x * 64 * (HKVn * DHn) + (h >> 2) * DHn;
    int a_m = tid >> 2, a_k = (tid & 3) * 4;
    int bn = tid >> 2, bkk = (tid & 3) * 4;
    float acc[4][4] = {};
    for (int k0 = 0; k0 < DHn; k0 += 16) {
        *(float4*)(&As[a_m][a_k]) = *(const float4*)(Ab + (size_t)a_m * Dm + k0 + a_k);
        float4 bv = *(const float4*)(Bb + (size_t)bn * (HKVn * DHn) + k0 + bkk);
        Bs[bkk + 0][bn] = bv.x; Bs[bkk + 1][bn] = bv.y;
        Bs[bkk + 2][bn] = bv.z; Bs[bkk + 3][bn] = bv.w;
        __syncthreads();
        mm_accum(As, Bs, acc, tid & 15, tid >> 4);
        __syncthreads();
    }
    int tx = tid & 15, ty = tid >> 4;
    float* out = sc + (size_t)h * Sm * Sm;
    int r0 = blockIdx.y * 64 + ty * 4, c0 = blockIdx.x * 64 + tx * 4;
    const float scale = 0.0883883476483184405f;
#pragma unroll
    for (int i = 0; i < 4; i++) {
        float4 o = make_float4(acc[i][0] * scale, acc[i][1] * scale,
                               acc[i][2] * scale, acc[i][3] * scale);
        *(float4*)(out + (size_t)(r0 + i) * Sm + c0) = o;
    }
}

__global__ void pv_kernel(const float* __restrict__ p, const float* __restrict__ v,
                          float* __restrict__ attn) {
    int h = blockIdx.z;
    __shared__ float As[64][20];
    __shared__ float Bs[16][68];
    int tid = threadIdx.x;
    const float* Ab = p + (size_t)h * Sm * Sm + (size_t)blockIdx.y * 64 * Sm;
    const float* Bb = v + (h >> 2) * DHn + blockIdx.x * 64;
    int a_m = tid >> 2, a_k = (tid & 3) * 4;
    int bk = (tid * 4) >> 6, bn = (tid * 4) & 63;
    float acc[4][4] = {};
    for (int k0 = 0; k0 < Sm; k0 += 16) {
        *(float4*)(&As[a_m][a_k]) = *(const float4*)(Ab + (size_t)a_m * Sm + k0 + a_k);
        *(float4*)(&Bs[bk][bn])   = *(const float4*)(Bb + (size_t)(k0 + bk) * (HKVn * DHn) + bn);
        __syncthreads();
        mm_accum(As, Bs, acc, tid & 15, tid >> 4);
        __syncthreads();
    }
    int tx = tid & 15, ty = tid >> 4;
    int r0 = blockIdx.y * 64 + ty * 4;
    int c0 = h * DHn + blockIdx.x * 64 + tx * 4;
#pragma unroll
    for (int i = 0; i < 4; i++) {
        float4 o = make_float4(acc[i][0], acc[i][1], acc[i][2], acc[i][3]);
        *(float4*)(attn + (size_t)(r0 + i) * Dm + c0) = o;
    }
}

// ---------------- launch ----------------
extern "C" void kernel_launch(void* const* d_in, const int* in_sizes, int n_in,
                              void* d_out, int out_size) {
    const float* hidden     = (const float*)d_in[0];
    const int*   amask      = (const int*)  d_in[1];
    const int*   pos        = (const int*)  d_in[2];
    const float* attn_nw    = (const float*)d_in[3];
    const float* wq         = (const float*)d_in[4];
    const float* wk         = (const float*)d_in[5];
    const float* wv         = (const float*)d_in[6];
    const float* wo         = (const float*)d_in[7];
    const float* ffn_nw     = (const float*)d_in[8];
    const float* router_w   = (const float*)d_in[9];
    const float* w_gate     = (const float*)d_in[10];
    const float* w_up       = (const float*)d_in[11];
    const float* w_down     = (const float*)d_in[12];
    const float* ws_gate    = (const float*)d_in[13];
    const float* ws_up      = (const float*)d_in[14];
    const float* ws_down    = (const float*)d_in[15];
    float* out = (float*)d_out;

    float *px, *pq, *pk, *pv, *psc, *pattn, *ph, *px2, *pts;
    float *peg, *peu, *pact, *prouted, *pgs, *pus, *psact, *pshared;
    int *pti;
    cudaGetSymbolAddress((void**)&px,      g_x);
    cudaGetSymbolAddress((void**)&pq,      g_q);
    cudaGetSymbolAddress((void**)&pk,      g_k);
    cudaGetSymbolAddress((void**)&pv,      g_v);
    cudaGetSymbolAddress((void**)&psc,     g_scores);
    cudaGetSymbolAddress((void**)&pattn,   g_attn);
    cudaGetSymbolAddress((void**)&ph,      g_h);
    cudaGetSymbolAddress((void**)&px2,     g_x2);
    cudaGetSymbolAddress((void**)&pti,     g_topidx);
    cudaGetSymbolAddress((void**)&pts,     g_topscore);
    cudaGetSymbolAddress((void**)&peg,     g_eg);
    cudaGetSymbolAddress((void**)&peu,     g_eu);
    cudaGetSymbolAddress((void**)&pact,    g_act);
    cudaGetSymbolAddress((void**)&prouted, g_routed);
    cudaGetSymbolAddress((void**)&pgs,     g_gs);
    cudaGetSymbolAddress((void**)&pus,     g_us);
    cudaGetSymbolAddress((void**)&psact,   g_sact);
    cudaGetSymbolAddress((void**)&pshared, g_shared);

    cudaFuncSetAttribute(hgemm_kernel, cudaFuncAttributeMaxDynamicSharedMemorySize, HG_SMEM);

    // --- attention block ---
    rmsnorm_kernel<<<Sm, 256>>>(hidden, attn_nw, px);
    hgemm_kernel<<<dim3(16, 4), 256, HG_SMEM>>>(px, Dm, wq, Dm,  pq, Dm,  nullptr, nullptr, Sm, 0);
    hgemm_kernel<<<dim3(4, 4),  256, HG_SMEM>>>(px, Dm, wk, 512, pk, 512, nullptr, nullptr, Sm, 0);
    hgemm_kernel<<<dim3(4, 4),  256, HG_SMEM>>>(px, Dm, wv, 512, pv, 512, nullptr, nullptr, Sm, 0);
    rope_kernel<<<Sm, 256>>>(pq, pk, pos);
    scores_kernel<<<dim3(8, 8, Hn), 256>>>(pq, pk, psc);
    softmax_kernel<<<dim3(Sm, Hn), 256>>>(psc, amask);
    pv_kernel<<<dim3(2, 8, Hn), 256>>>(psc, pv, pattn);
    hgemm_kernel<<<dim3(16, 4), 256, HG_SMEM>>>(pattn, Dm, wo, Dm, ph, Dm, hidden, nullptr, Sm, 0);

    // --- MoE block ---
    rmsnorm_kernel<<<Sm, 256>>>(ph, ffn_nw, px2);
    router_kernel<<<Sm, 256>>>(px2, router_w, pti, pts);
    dispatch_kernel<<<1, Sm>>>(pti);
    hgemm_kernel<<<dim3(16, 4, En), 256, HG_SMEM>>>(px2,  Dm, w_gate, Fn, peg,     Fn, nullptr, pts,     Sm, 1);
    hgemm_kernel<<<dim3(16, 4, En), 256, HG_SMEM>>>(px2,  Dm, w_up,   Fn, peu,     Fn, nullptr, pts,     Sm, 1);
    silumul_kernel<<<(Sm * Fn) / 256, 256>>>(peg, peu, pact, Sm * Fn);
    hgemm_kernel<<<dim3(16, 4, En), 256, HG_SMEM>>>(pact, Fn, w_down, Dm, prouted, Dm, nullptr, nullptr, Sm, 1);

    // shared expert
    hgemm_kernel<<<dim3(16, 4), 256, HG_SMEM>>>(px2,   Dm, ws_gate, Fn, pgs,     Fn, nullptr, nullptr, Sm, 0);
    hgemm_kernel<<<dim3(16, 4), 256, HG_SMEM>>>(px2,   Dm, ws_up,   Fn, pus,     Fn, nullptr, nullptr, Sm, 0);
    silumul_kernel<<<(Sm * Fn) / 256, 256>>>(pgs, pus, psact, Sm * Fn);
    hgemm_kernel<<<dim3(16, 4), 256, HG_SMEM>>>(psact, Fn, ws_down, Dm, pshared, Dm, nullptr, nullptr, Sm, 0);

    // final: out = h + routed + shared
    add3_kernel<<<(Sm * Dm) / 256, 256>>>(ph, prouted, pshared, out);
}

// round 5
// speedup vs baseline: 2.3975x; 2.1690x over previous
#include <cuda_runtime.h>
#include <cuda_bf16.h>
#include <stdint.h>
#include <math.h>

#define Dm   2048
#define Sm   512
#define Hn   16
#define HKVn 4
#define DHn  128
#define Fn   2048
#define En   8
#define QKVP 3072

// ---------------- scratch (device globals) ----------------
__device__ float g_qkv[Sm*QKVP];
__device__ float g_scores[Hn*Sm*Sm];
__device__ float g_h[Sm*Dm];
__device__ float g_x2f[Sm*Dm];
__device__ float g_gu[Sm*4096];
__device__ float g_sgu[Sm*4096];
__device__ float g_routed[Sm*Dm];
__device__ float g_shared[Sm*Dm];
__device__ int   g_topidx[Sm];
__device__ float g_topscore[Sm];
__device__ int   g_cnt[En];
__device__ int   g_list[En*Sm];

// activation bf16 hi/lo planes [512][2048]
__device__ __nv_bfloat16 x_h[Sm*Dm],  x_l[Sm*Dm];
__device__ __nv_bfloat16 at_h[Sm*Dm], at_l[Sm*Dm];
__device__ __nv_bfloat16 x2_h[Sm*Dm], x2_l[Sm*Dm];
__device__ __nv_bfloat16 ac_h[Sm*Dm], ac_l[Sm*Dm];
__device__ __nv_bfloat16 sa_h[Sm*Dm], sa_l[Sm*Dm];

// converted weight planes
__device__ __nv_bfloat16 cw_qkv_h[2048*3072], cw_qkv_l[2048*3072];
__device__ __nv_bfloat16 cw_wo_h [2048*2048], cw_wo_l [2048*2048];
__device__ __nv_bfloat16 cw_gu_h [8*2048*4096], cw_gu_l [8*2048*4096];
__device__ __nv_bfloat16 cw_dn_h [8*2048*2048], cw_dn_l [8*2048*2048];
__device__ __nv_bfloat16 cw_sgu_h[2048*4096], cw_sgu_l[2048*4096];
__device__ __nv_bfloat16 cw_sdn_h[2048*2048], cw_sdn_l[2048*2048];

// ---------------- helpers ----------------
__device__ __forceinline__ uint32_t smem_u32(const void* p) {
    uint32_t a;
    asm("{ .reg .u64 t; cvta.to.shared.u64 t, %1; cvt.u32.u64 %0, t; }" : "=r"(a) : "l"(p));
    return a;
}
// a -> low half (element k even), b -> high half (element k+1)
__device__ __forceinline__ uint32_t pack_bf16x2(float a, float b) {
    uint32_t r;
    asm("cvt.rn.bf16x2.f32 %0, %1, %2;" : "=r"(r) : "f"(b), "f"(a));
    return r;
}
__device__ __forceinline__ void mma16816(float c[4], const uint32_t a[4], const uint32_t b[2]) {
    asm volatile(
        "mma.sync.aligned.m16n8k16.row.col.f32.bf16.bf16.f32 "
        "{%0,%1,%2,%3}, {%4,%5,%6,%7}, {%8,%9}, {%0,%1,%2,%3};"
        : "+f"(c[0]), "+f"(c[1]), "+f"(c[2]), "+f"(c[3])
        : "r"(a[0]), "r"(a[1]), "r"(a[2]), "r"(a[3]), "r"(b[0]), "r"(b[1]));
}
__device__ __forceinline__ void cpa16(uint32_t d, const void* s) {
    asm volatile("cp.async.cg.shared.global [%0], [%1], 16;" :: "r"(d), "l"(s));
}
#define CPA_COMMIT() asm volatile("cp.async.commit_group;" ::: "memory")
#define CPA_WAIT1()  asm volatile("cp.async.wait_group 1;" ::: "memory")
#define CPA_WAIT0()  asm volatile("cp.async.wait_group 0;" ::: "memory")
__device__ __forceinline__ void ldm_x4(uint32_t r[4], uint32_t a) {
    asm volatile("ldmatrix.sync.aligned.m8n8.x4.shared.b16 {%0,%1,%2,%3}, [%4];"
        : "=r"(r[0]), "=r"(r[1]), "=r"(r[2]), "=r"(r[3]) : "r"(a));
}
__device__ __forceinline__ void ldm_x4t(uint32_t r[4], uint32_t a) {
    asm volatile("ldmatrix.sync.aligned.m8n8.x4.trans.shared.b16 {%0,%1,%2,%3}, [%4];"
        : "=r"(r[0]), "=r"(r[1]), "=r"(r[2]), "=r"(r[3]) : "r"(a));
}

// ---------------- weight conversion: fp32 [rows][scols] -> hi/lo planes ----------------
__global__ void convw_kernel(const float* __restrict__ src,
                             __nv_bfloat16* __restrict__ dhi,
                             __nv_bfloat16* __restrict__ dlo,
                             int scols, int dpitch, int coff, int n4) {
    int i = blockIdx.x * 256 + threadIdx.x;
    if (i >= n4) return;
    float4 v = ((const float4*)src)[i];
    int e = i * 4;
    int row = e / scols, col = e % scols;
    uint32_t h01 = pack_bf16x2(v.x, v.y);
    uint32_t h23 = pack_bf16x2(v.z, v.w);
    float lx = v.x - __uint_as_float(h01 << 16);
    float ly = v.y - __uint_as_float(h01 & 0xffff0000u);
    float lz = v.z - __uint_as_float(h23 << 16);
    float lw = v.w - __uint_as_float(h23 & 0xffff0000u);
    uint32_t l01 = pack_bf16x2(lx, ly);
    uint32_t l23 = pack_bf16x2(lz, lw);
    size_t d = (size_t)row * dpitch + coff + col;
    *(uint2*)(dhi + d) = make_uint2(h01, h23);
    *(uint2*)(dlo + d) = make_uint2(l01, l23);
}

// =============== bf16 3-pass HMMA GEMM, 64x128 tile, cp.async + ldmatrix ===============
// smem stage layout (bf16 elems): AH[64][72] @0, AL @4608, BH[64][136] @9216, BL @17920
#define STAGE_E 26624
#define STAGE_B (STAGE_E*2)
#define TG_SMEM (2*STAGE_B)   // 106496 bytes

__global__ void __launch_bounds__(256, 2) tgemm_kernel(
    const __nv_bfloat16* __restrict__ aH, const __nv_bfloat16* __restrict__ aL,
    const __nv_bfloat16* __restrict__ bHp, const __nv_bfloat16* __restrict__ bLp,
    int ldb, float* __restrict__ C, int ldc,
    const float* __restrict__ res, const float* __restrict__ rowscale, int gather)
{
    extern __shared__ __nv_bfloat16 smb[];
    __shared__ int   tok[64];
    __shared__ float scl[64];
    int row0 = blockIdx.y * 64;
    int n0   = blockIdx.x * 128;
    int tid  = threadIdx.x;

    if (gather) {
        int e = blockIdx.z;
        int count = g_cnt[e];
        if (row0 >= count) return;
        bHp += (size_t)e * 2048 * ldb;
        bLp += (size_t)e * 2048 * ldb;
        if (tid < 64) {
            int r = row0 + tid;
            int t = (r < count) ? g_list[e * Sm + r] : -1;
            tok[tid] = t;
            scl[tid] = (t >= 0 && rowscale) ? rowscale[t] : 1.0f;
        }
    } else {
        if (tid < 64) { tok[tid] = row0 + tid; scl[tid] = 1.0f; }
    }
    __syncthreads();

    uint32_t smbase = smem_u32(smb);
    int lane = tid & 31, wid = tid >> 5;
    int gr = lane >> 2, tg = lane & 3;
    int wm = wid >> 2, wn = wid & 3;     // 2 x 4 warps; warp tile 32x32

    float acc[2][4][4];
#pragma unroll
    for (int i = 0; i < 2; i++)
#pragma unroll
        for (int j = 0; j < 4; j++)
#pragma unroll
            for (int r = 0; r < 4; r++) acc[i][j][r] = 0.f;

    // ---- copy stage macro-ish lambda ----
    auto copy_stage = [&](int st) {
        uint32_t base = smbase + (uint32_t)(st & 1) * STAGE_B;
        int k0 = st * 64;
        // A planes: 64 rows x 64 k, 8 chunks/row
#pragma unroll
        for (int pl = 0; pl < 2; pl++) {
            const __nv_bfloat16* asrc = pl ? aL : aH;
            uint32_t d0 = base + (pl ? 4608 : 0) * 2;
#pragma unroll
            for (int it = 0; it < 2; it++) {
                int idx = it * 256 + tid;
                int row = idx >> 3, ch = idx & 7;
                int t = tok[row];
                int grow = t < 0 ? 0 : t;
                cpa16(d0 + (uint32_t)(row * 72 + ch * 8) * 2,
                      asrc + (size_t)grow * 2048 + k0 + ch * 8);
            }
        }
        // B planes: 64 k rows x 128 n, 16 chunks/row
#pragma unroll
        for (int pl = 0; pl < 2; pl++) {
            const __nv_bfloat16* bsrc = pl ? bLp : bHp;
            uint32_t d0 = base + (pl ? 17920 : 9216) * 2;
#pragma unroll
            for (int it = 0; it < 4; it++) {
                int idx = it * 256 + tid;
                int row = idx >> 4, ch = idx & 15;
                cpa16(d0 + (uint32_t)(row * 136 + ch * 8) * 2,
                      bsrc + (size_t)(k0 + row) * ldb + n0 + ch * 8);
            }
        }
        CPA_COMMIT();
    };

    copy_stage(0);

    int lr = lane & 15;
    int lc8 = (lane & 16) >> 1;   // 0 or 8

    for (int st = 0; st < 32; st++) {
        if (st + 1 < 32) { copy_stage(st + 1); CPA_WAIT1(); }
        else             { CPA_WAIT0(); }
        __syncthreads();

        uint32_t base = smbase + (uint32_t)(st & 1) * STAGE_B;
        uint32_t AHb = base, ALb = base + 9216;
        uint32_t BHb = base + 18432, BLb = base + 35840;

#pragma unroll
        for (int ks = 0; ks < 4; ks++) {
            uint32_t fAH[2][4], fAL[2][4], fBH[4][2], fBL[4][2];
#pragma unroll
            for (int mt = 0; mt < 2; mt++) {
                uint32_t ao = (uint32_t)((wm * 32 + mt * 16 + lr) * 72 + ks * 16 + lc8) * 2;
                ldm_x4(fAH[mt], AHb + ao);
                ldm_x4(fAL[mt], ALb + ao);
            }
#pragma unroll
            for (int half = 0; half < 2; half++) {
                int brow = ks * 16 + lr;
                int bcol = wn * 32 + half * 16 + lc8;
                uint32_t bo = (uint32_t)(brow * 136 + bcol) * 2;
                uint32_t rH[4], rL[4];
                ldm_x4t(rH, BHb + bo);
                ldm_x4t(rL, BLb + bo);
                fBH[half*2][0] = rH[0]; fBH[half*2][1] = rH[1];
                fBH[half*2+1][0] = rH[2]; fBH[half*2+1][1] = rH[3];
                fBL[half*2][0] = rL[0]; fBL[half*2][1] = rL[1];
                fBL[half*2+1][0] = rL[2]; fBL[half*2+1][1] = rL[3];
            }
#pragma unroll
            for (int mt = 0; mt < 2; mt++)
#pragma unroll
                for (int nt = 0; nt < 4; nt++) {
                    mma16816(acc[mt][nt], fAH[mt], fBH[nt]);
                    mma16816(acc[mt][nt], fAH[mt], fBL[nt]);
                    mma16816(acc[mt][nt], fAL[mt], fBH[nt]);
                }
        }
        __syncthreads();
    }

    // ---- epilogue ----
#pragma unroll
    for (int mt = 0; mt < 2; mt++) {
        int r1 = wm * 32 + mt * 16 + gr;
        int r2 = r1 + 8;
        int t1 = tok[r1], t2 = tok[r2];
        float s1 = scl[r1], s2 = scl[r2];
#pragma unroll
        for (int nt = 0; nt < 4; nt++) {
            int col = n0 + wn * 32 + nt * 8 + tg * 2;
            if (t1 >= 0) {
                float2 o = make_float2(acc[mt][nt][0] * s1, acc[mt][nt][1] * s1);
                if (res) {
                    float2 rv = *(const float2*)(res + (size_t)t1 * ldc + col);
                    o.x += rv.x; o.y += rv.y;
                }
                *(float2*)(C + (size_t)t1 * ldc + col) = o;
            }
            if (t2 >= 0) {
                float2 o = make_float2(acc[mt][nt][2] * s2, acc[mt][nt][3] * s2);
                if (res) {
                    float2 rv = *(const float2*)(res + (size_t)t2 * ldc + col);
                    o.x += rv.x; o.y += rv.y;
                }
                *(float2*)(C + (size_t)t2 * ldc + col) = o;
            }
        }
    }
}

// ---------------- small kernels ----------------
__global__ void rmsnorm_kernel(const float* __restrict__ in, const float* __restrict__ w,
                               float* __restrict__ outf,
                               __nv_bfloat16* __restrict__ outh,
                               __nv_bfloat16* __restrict__ outl) {
    int t = blockIdx.x;
    const float* row = in + (size_t)t * Dm;
    float s = 0.f;
    for (int d = threadIdx.x; d < Dm; d += 256) { float v = row[d]; s += v * v; }
    __shared__ float red[256];
    red[threadIdx.x] = s; __syncthreads();
    for (int off = 128; off > 0; off >>= 1) {
        if (threadIdx.x < off) red[threadIdx.x] += red[threadIdx.x + off];
        __syncthreads();
    }
    float r = rsqrtf(red[0] / (float)Dm + 1e-5f);
    for (int d = threadIdx.x; d < Dm; d += 256) {
        float v = row[d] * r * w[d];
        if (outf) outf[(size_t)t * Dm + d] = v;
        __nv_bfloat16 h = __float2bfloat16(v);
        outh[(size_t)t * Dm + d] = h;
        outl[(size_t)t * Dm + d] = __float2bfloat16(v - __bfloat162float(h));
    }
}

__global__ void rope_kernel(float* __restrict__ qkv, const int* __restrict__ pos_ids) {
    int t = blockIdx.x;
    float p = (float)pos_ids[t];
    for (int idx = threadIdx.x; idx < (Hn + HKVn) * 64; idx += blockDim.x) {
        int head = idx >> 6;
        int i = idx & 63;
        float inv = powf(500000.0f, -(float)i / 64.0f);
        float f = p * inv;
        float sn, cs;
        sincosf(f, &sn, &cs);
        float* base;
        if (head < Hn) base = qkv + (size_t)t * QKVP + head * DHn;
        else           base = qkv + (size_t)t * QKVP + 2048 + (head - Hn) * DHn;
        float x1 = base[i], x2 = base[i + 64];
        base[i]      = x1 * cs - x2 * sn;
        base[i + 64] = x2 * cs + x1 * sn;
    }
}

__global__ void softmax_kernel(float* __restrict__ sc, const int* __restrict__ mask) {
    int i = blockIdx.x;
    int h = blockIdx.y;
    float* row = sc + ((size_t)h * Sm + i) * Sm;
    int tid = threadIdx.x;
    int j0 = tid, j1 = tid + 256;
    float s0 = (j0 <= i && mask[j0] > 0) ? row[j0] : -1e9f;
    float s1 = (j1 <= i && mask[j1] > 0) ? row[j1] : -1e9f;
    __shared__ float red[256];
    red[tid] = fmaxf(s0, s1); __syncthreads();
    for (int off = 128; off > 0; off >>= 1) {
        if (tid < off) red[tid] = fmaxf(red[tid], red[tid + off]);
        __syncthreads();
    }
    float m = red[0];
    __syncthreads();
    float e0 = expf(s0 - m), e1 = expf(s1 - m);
    red[tid] = e0 + e1; __syncthreads();
    for (int off = 128; off > 0; off >>= 1) {
        if (tid < off) red[tid] += red[tid + off];
        __syncthreads();
    }
    float inv = 1.f / red[0];
    row[j0] = e0 * inv;
    row[j1] = e1 * inv;
}

__global__ void router_kernel(const float* __restrict__ x2, const float* __restrict__ rw,
                              int* __restrict__ topidx, float* __restrict__ topscore) {
    int t = blockIdx.x;
    int w = threadIdx.x >> 5, lane = threadIdx.x & 31;
    float s = 0.f;
    for (int d = lane; d < Dm; d += 32)
        s += x2[(size_t)t * Dm + d] * rw[d * En + w];
    for (int off = 16; off; off >>= 1) s += __shfl_down_sync(0xffffffff, s, off);
    __shared__ float logits[En];
    if (lane == 0) logits[w] = s;
    __syncthreads();
    if (threadIdx.x == 0) {
        int best = 0; float bv = logits[0];
        for (int e = 1; e < En; e++) if (logits[e] > bv) { bv = logits[e]; best = e; }
        topidx[t] = best;
        topscore[t] = 1.f / (1.f + expf(-bv));
    }
}

__global__ void dispatch_kernel(const int* __restrict__ topidx) {
    int t = threadIdx.x;
    if (t < En) g_cnt[t] = 0;
    __syncthreads();
    int e = topidx[t];
    int pos = atomicAdd(&g_cnt[e], 1);
    g_list[e * Sm + pos] = t;
}

// act = silu(gu[:, :2048]) * gu[:, 2048:]; write hi/lo planes
__global__ void silumul_kernel(const float* __restrict__ gu,
                               __nv_bfloat16* __restrict__ outh,
                               __nv_bfloat16* __restrict__ outl) {
    int i = blockIdx.x * 256 + threadIdx.x;
    int t = i >> 11, j = i & 2047;
    float g = gu[(size_t)t * 4096 + j];
    float u = gu[(size_t)t * 4096 + 2048 + j];
    float a = (g / (1.f + expf(-g))) * u;
    __nv_bfloat16 h = __float2bfloat16(a);
    outh[i] = h;
    outl[i] = __float2bfloat16(a - __bfloat162float(h));
}

__global__ void add3_kernel(const float* __restrict__ a, const float* __restrict__ b,
                            const float* __restrict__ c, float* __restrict__ out) {
    int i = blockIdx.x * 256 + threadIdx.x;
    out[i] = a[i] + b[i] + c[i];
}

// ---------------- fp32 attention (scores / pv) ----------------
__device__ __forceinline__ void mm_accum(const float (*As)[20], const float (*Bs)[68],
                                         float acc[4][4], int tx, int ty) {
#pragma unroll
    for (int kk = 0; kk < 16; kk++) {
        float a[4];
#pragma unroll
        for (int i = 0; i < 4; i++) a[i] = As[ty * 4 + i][kk];
        float4 b = *(const float4*)(&Bs[kk][tx * 4]);
#pragma unroll
        for (int i = 0; i < 4; i++) {
            acc[i][0] += a[i] * b.x;
            acc[i][1] += a[i] * b.y;
            acc[i][2] += a[i] * b.z;
            acc[i][3] += a[i] * b.w;
        }
    }
}

__global__ void scores_kernel(const float* __restrict__ qkv, float* __restrict__ sc) {
    int h = blockIdx.z;
    __shared__ float As[64][20];
    __shared__ float Bs[16][68];
    int tid = threadIdx.x;
    const float* Ab = qkv + (size_t)blockIdx.y * 64 * QKVP + h * DHn;
    const float* Bb = qkv + (size_t)blockIdx.x * 64 * QKVP + 2048 + (h >> 2) * DHn;
    int a_m = tid >> 2, a_k = (tid & 3) * 4;
    int bn = tid >> 2, bkk = (tid & 3) * 4;
    float acc[4][4] = {};
    for (int k0 = 0; k0 < DHn; k0 += 16) {
        *(float4*)(&As[a_m][a_k]) = *(const float4*)(Ab + (size_t)a_m * QKVP + k0 + a_k);
        float4 bv = *(const float4*)(Bb + (size_t)bn * QKVP + k0 + bkk);
        Bs[bkk + 0][bn] = bv.x; Bs[bkk + 1][bn] = bv.y;
        Bs[bkk + 2][bn] = bv.z; Bs[bkk + 3][bn] = bv.w;
        __syncthreads();
        mm_accum(As, Bs, acc, tid & 15, tid >> 4);
        __syncthreads();
    }
    int tx = tid & 15, ty = tid >> 4;
    float* out = sc + (size_t)h * Sm * Sm;
    int r0 = blockIdx.y * 64 + ty * 4, c0 = blockIdx.x * 64 + tx * 4;
    const float scale = 0.0883883476483184405f;
#pragma unroll
    for (int i = 0; i < 4; i++) {
        float4 o = make_float4(acc[i][0] * scale, acc[i][1] * scale,
                               acc[i][2] * scale, acc[i][3] * scale);
        *(float4*)(out + (size_t)(r0 + i) * Sm + c0) = o;
    }
}

__global__ void pv_kernel(const float* __restrict__ p, const float* __restrict__ qkv,
                          __nv_bfloat16* __restrict__ outh, __nv_bfloat16* __restrict__ outl) {
    int h = blockIdx.z;
    __shared__ float As[64][20];
    __shared__ float Bs[16][68];
    int tid = threadIdx.x;
    const float* Ab = p + (size_t)h * Sm * Sm + (size_t)blockIdx.y * 64 * Sm;
    const float* Bb = qkv + 2560 + (h >> 2) * DHn + blockIdx.x * 64;
    int a_m = tid >> 2, a_k = (tid & 3) * 4;
    int bk = (tid * 4) >> 6, bn = (tid * 4) & 63;
    float acc[4][4] = {};
    for (int k0 = 0; k0 < Sm; k0 += 16) {
        *(float4*)(&As[a_m][a_k]) = *(const float4*)(Ab + (size_t)a_m * Sm + k0 + a_k);
        *(float4*)(&Bs[bk][bn])   = *(const float4*)(Bb + (size_t)(k0 + bk) * QKVP + bn);
        __syncthreads();
        mm_accum(As, Bs, acc, tid & 15, tid >> 4);
        __syncthreads();
    }
    int tx = tid & 15, ty = tid >> 4;
    int r0 = blockIdx.y * 64 + ty * 4;
    int c0 = h * DHn + blockIdx.x * 64 + tx * 4;
#pragma unroll
    for (int i = 0; i < 4; i++) {
        float4 o = make_float4(acc[i][0], acc[i][1], acc[i][2], acc[i][3]);
        uint32_t h01 = pack_bf16x2(o.x, o.y);
        uint32_t h23 = pack_bf16x2(o.z, o.w);
        float lx = o.x - __uint_as_float(h01 << 16);
        float ly = o.y - __uint_as_float(h01 & 0xffff0000u);
        float lz = o.z - __uint_as_float(h23 << 16);
        float lw = o.w - __uint_as_float(h23 & 0xffff0000u);
        uint32_t l01 = pack_bf16x2(lx, ly);
        uint32_t l23 = pack_bf16x2(lz, lw);
        size_t d = (size_t)(r0 + i) * Dm + c0;
        *(uint2*)(outh + d) = make_uint2(h01, h23);
        *(uint2*)(outl + d) = make_uint2(l01, l23);
    }
}

// ---------------- launch ----------------
#define GSYM(p, s) cudaGetSymbolAddress((void**)&p, s)

extern "C" void kernel_launch(void* const* d_in, const int* in_sizes, int n_in,
                              void* d_out, int out_size) {
    const float* hidden   = (const float*)d_in[0];
    const int*   amask    = (const int*)  d_in[1];
    const int*   pos      = (const int*)  d_in[2];
    const float* attn_nw  = (const float*)d_in[3];
    const float* wq       = (const float*)d_in[4];
    const float* wk       = (const float*)d_in[5];
    const float* wv       = (const float*)d_in[6];
    const float* wo       = (const float*)d_in[7];
    const float* ffn_nw   = (const float*)d_in[8];
    const float* router_w = (const float*)d_in[9];
    const float* w_gate   = (const float*)d_in[10];
    const float* w_up     = (const float*)d_in[11];
    const float* w_down   = (const float*)d_in[12];
    const float* ws_gate  = (const float*)d_in[13];
    const float* ws_up    = (const float*)d_in[14];
    const float* ws_down  = (const float*)d_in[15];
    float* out = (float*)d_out;

    float *pqkv, *psc, *ph, *px2f, *pgu, *psgu, *prouted, *pshared, *pts;
    int *pti;
    __nv_bfloat16 *pxh, *pxl, *path, *patl, *px2h, *px2l, *pach, *pacl, *psah, *psal;
    __nv_bfloat16 *pwqkvh, *pwqkvl, *pwoh, *pwol, *pguh, *pgul, *pdnh, *pdnl,
                  *psguh, *psgul, *psdnh, *psdnl;
    GSYM(pqkv, g_qkv); GSYM(psc, g_scores); GSYM(ph, g_h); GSYM(px2f, g_x2f);
    GSYM(pgu, g_gu); GSYM(psgu, g_sgu); GSYM(prouted, g_routed); GSYM(pshared, g_shared);
    GSYM(pti, g_topidx); GSYM(pts, g_topscore);
    GSYM(pxh, x_h); GSYM(pxl, x_l); GSYM(path, at_h); GSYM(patl, at_l);
    GSYM(px2h, x2_h); GSYM(px2l, x2_l); GSYM(pach, ac_h); GSYM(pacl, ac_l);
    GSYM(psah, sa_h); GSYM(psal, sa_l);
    GSYM(pwqkvh, cw_qkv_h); GSYM(pwqkvl, cw_qkv_l);
    GSYM(pwoh, cw_wo_h); GSYM(pwol, cw_wo_l);
    GSYM(pguh, cw_gu_h); GSYM(pgul, cw_gu_l);
    GSYM(pdnh, cw_dn_h); GSYM(pdnl, cw_dn_l);
    GSYM(psguh, cw_sgu_h); GSYM(psgul, cw_sgu_l);
    GSYM(psdnh, cw_sdn_h); GSYM(psdnl, cw_sdn_l);

    cudaFuncSetAttribute(tgemm_kernel, cudaFuncAttributeMaxDynamicSharedMemorySize, TG_SMEM);

    // --- weight conversion (bf16 hi/lo planes, fused layouts) ---
    convw_kernel<<<2048*2048/1024, 256>>>(wq, pwqkvh, pwqkvl, 2048, 3072, 0,    2048*2048/4);
    convw_kernel<<<2048*512/1024,  256>>>(wk, pwqkvh, pwqkvl, 512,  3072, 2048, 2048*512/4);
    convw_kernel<<<2048*512/1024,  256>>>(wv, pwqkvh, pwqkvl, 512,  3072, 2560, 2048*512/4);
    convw_kernel<<<2048*2048/1024, 256>>>(wo, pwoh, pwol, 2048, 2048, 0, 2048*2048/4);
    convw_kernel<<<8*2048*2048/1024, 256>>>(w_gate, pguh, pgul, 2048, 4096, 0,    8*2048*2048/4);
    convw_kernel<<<8*2048*2048/1024, 256>>>(w_up,   pguh, pgul, 2048, 4096, 2048, 8*2048*2048/4);
    convw_kernel<<<8*2048*2048/1024, 256>>>(w_down, pdnh, pdnl, 2048, 2048, 0,    8*2048*2048/4);
    convw_kernel<<<2048*2048/1024, 256>>>(ws_gate, psguh, psgul, 2048, 4096, 0,    2048*2048/4);
    convw_kernel<<<2048*2048/1024, 256>>>(ws_up,   psguh, psgul, 2048, 4096, 2048, 2048*2048/4);
    convw_kernel<<<2048*2048/1024, 256>>>(ws_down, psdnh, psdnl, 2048, 2048, 0, 2048*2048/4);

    // --- attention block ---
    rmsnorm_kernel<<<Sm, 256>>>(hidden, attn_nw, nullptr, pxh, pxl);
    tgemm_kernel<<<dim3(24, 8), 256, TG_SMEM>>>(pxh, pxl, pwqkvh, pwqkvl, 3072,
                                                pqkv, 3072, nullptr, nullptr, 0);
    rope_kernel<<<Sm, 256>>>(pqkv, pos);
    scores_kernel<<<dim3(8, 8, Hn), 256>>>(pqkv, psc);
    softmax_kernel<<<dim3(Sm, Hn), 256>>>(psc, amask);
    pv_kernel<<<dim3(2, 8, Hn), 256>>>(psc, pqkv, path, patl);
    tgemm_kernel<<<dim3(16, 8), 256, TG_SMEM>>>(path, patl, pwoh, pwol, 2048,
                                                ph, 2048, hidden, nullptr, 0);

    // --- MoE block ---
    rmsnorm_kernel<<<Sm, 256>>>(ph, ffn_nw, px2f, px2h, px2l);
    router_kernel<<<Sm, 256>>>(px2f, router_w, pti, pts);
    dispatch_kernel<<<1, Sm>>>(pti);
    tgemm_kernel<<<dim3(32, 8, En), 256, TG_SMEM>>>(px2h, px2l, pguh, pgul, 4096,
                                                    pgu, 4096, nullptr, pts, 1);
    silumul_kernel<<<(Sm * Dm) / 256, 256>>>(pgu, pach, pacl);
    tgemm_kernel<<<dim3(16, 8, En), 256, TG_SMEM>>>(pach, pacl, pdnh, pdnl, 2048,
                                                    prouted, 2048, nullptr, nullptr, 1);

    // shared expert
    tgemm_kernel<<<dim3(32, 8), 256, TG_SMEM>>>(px2h, px2l, psguh, psgul, 4096,
                                                psgu, 4096, nullptr, nullptr, 0);
    silumul_kernel<<<(Sm * Dm) / 256, 256>>>(psgu, psah, psal);
    tgemm_kernel<<<dim3(16, 8), 256, TG_SMEM>>>(psah, psal, psdnh, psdnl, 2048,
                                                pshared, 2048, nullptr, nullptr, 0);

    // final: out = h + routed + shared
    add3_kernel<<<(Sm * Dm) / 256, 256>>>(ph, prouted, pshared, out);
}

// round 6
// speedup vs baseline: 2.5394x; 1.0592x over previous
#include <cuda_runtime.h>
#include <cuda_bf16.h>
#include <stdint.h>
#include <math.h>

#define Dm   2048
#define Sm   512
#define Hn   16
#define HKVn 4
#define DHn  128
#define Fn   2048
#define En   8
#define QKVP 3072

// ---------------- scratch (device globals) ----------------
__device__ float g_qkv[Sm*QKVP];
__device__ float g_scores[Hn*Sm*Sm];
__device__ float g_h[Sm*Dm];
__device__ float g_x2f[Sm*Dm];
__device__ float g_gu[Sm*4096];
__device__ float g_sgu[Sm*4096];
__device__ float g_routed[Sm*Dm];
__device__ float g_shared[Sm*Dm];
__device__ int   g_topidx[Sm];
__device__ float g_topscore[Sm];
__device__ int   g_cnt[En];
__device__ int   g_list[En*Sm];

// activation bf16 hi/lo planes
__device__ __nv_bfloat16 x_h[Sm*Dm],  x_l[Sm*Dm];
__device__ __nv_bfloat16 at_h[Sm*Dm], at_l[Sm*Dm];
__device__ __nv_bfloat16 x2_h[Sm*Dm], x2_l[Sm*Dm];
__device__ __nv_bfloat16 ac_h[Sm*Dm], ac_l[Sm*Dm];
__device__ __nv_bfloat16 sa_h[Sm*Dm], sa_l[Sm*Dm];
// attention planes
__device__ __nv_bfloat16 q_h[Sm*Dm],  q_l[Sm*Dm];
__device__ __nv_bfloat16 k_h[Sm*512], k_l[Sm*512];
__device__ __nv_bfloat16 v_h[Sm*512], v_l[Sm*512];
__device__ __nv_bfloat16 p_h[Hn*Sm*Sm], p_l[Hn*Sm*Sm];

// converted weight planes
__device__ __nv_bfloat16 cw_qkv_h[2048*3072], cw_qkv_l[2048*3072];
__device__ __nv_bfloat16 cw_wo_h [2048*2048], cw_wo_l [2048*2048];
__device__ __nv_bfloat16 cw_gu_h [8*2048*4096], cw_gu_l [8*2048*4096];
__device__ __nv_bfloat16 cw_dn_h [8*2048*2048], cw_dn_l [8*2048*2048];
__device__ __nv_bfloat16 cw_sgu_h[2048*4096], cw_sgu_l[2048*4096];
__device__ __nv_bfloat16 cw_sdn_h[2048*2048], cw_sdn_l[2048*2048];

// ---------------- helpers ----------------
__device__ __forceinline__ uint32_t smem_u32(const void* p) {
    uint32_t a;
    asm("{ .reg .u64 t; cvta.to.shared.u64 t, %1; cvt.u32.u64 %0, t; }" : "=r"(a) : "l"(p));
    return a;
}
// a -> low element, b -> high element
__device__ __forceinline__ uint32_t pack_bf16x2(float a, float b) {
    uint32_t r;
    asm("cvt.rn.bf16x2.f32 %0, %1, %2;" : "=r"(r) : "f"(b), "f"(a));
    return r;
}
__device__ __forceinline__ void mma16816(float c[4], const uint32_t a[4], const uint32_t b[2]) {
    asm volatile(
        "mma.sync.aligned.m16n8k16.row.col.f32.bf16.bf16.f32 "
        "{%0,%1,%2,%3}, {%4,%5,%6,%7}, {%8,%9}, {%0,%1,%2,%3};"
        : "+f"(c[0]), "+f"(c[1]), "+f"(c[2]), "+f"(c[3])
        : "r"(a[0]), "r"(a[1]), "r"(a[2]), "r"(a[3]), "r"(b[0]), "r"(b[1]));
}
__device__ __forceinline__ void cpa16(uint32_t d, const void* s) {
    asm volatile("cp.async.cg.shared.global [%0], [%1], 16;" :: "r"(d), "l"(s));
}
#define CPA_COMMIT() asm volatile("cp.async.commit_group;" ::: "memory")
#define CPA_WAIT1()  asm volatile("cp.async.wait_group 1;" ::: "memory")
#define CPA_WAIT0()  asm volatile("cp.async.wait_group 0;" ::: "memory")
__device__ __forceinline__ void ldm_x4(uint32_t r[4], uint32_t a) {
    asm volatile("ldmatrix.sync.aligned.m8n8.x4.shared.b16 {%0,%1,%2,%3}, [%4];"
        : "=r"(r[0]), "=r"(r[1]), "=r"(r[2]), "=r"(r[3]) : "r"(a));
}
__device__ __forceinline__ void ldm_x4t(uint32_t r[4], uint32_t a) {
    asm volatile("ldmatrix.sync.aligned.m8n8.x4.trans.shared.b16 {%0,%1,%2,%3}, [%4];"
        : "=r"(r[0]), "=r"(r[1]), "=r"(r[2]), "=r"(r[3]) : "r"(a));
}
__device__ __forceinline__ void split_store(float v, __nv_bfloat16* ph, __nv_bfloat16* pl, size_t off) {
    __nv_bfloat16 h = __float2bfloat16(v);
    ph[off] = h;
    pl[off] = __float2bfloat16(v - __bfloat162float(h));
}

// ---------------- weight conversion: fp32 -> hi/lo planes (8 elems/thread) ----------------
__global__ void convw_kernel(const float* __restrict__ src,
                             __nv_bfloat16* __restrict__ dhi,
                             __nv_bfloat16* __restrict__ dlo,
                             int scols, int dpitch, int coff, int n8) {
    int i = blockIdx.x * 256 + threadIdx.x;
    if (i >= n8) return;
    const float4* s4 = (const float4*)src;
    float4 va = __ldcs(s4 + i * 2);
    float4 vb = __ldcs(s4 + i * 2 + 1);
    int e = i * 8;
    int row = e / scols, col = e % scols;
    uint32_t h01 = pack_bf16x2(va.x, va.y), h23 = pack_bf16x2(va.z, va.w);
    uint32_t h45 = pack_bf16x2(vb.x, vb.y), h67 = pack_bf16x2(vb.z, vb.w);
    uint32_t l01 = pack_bf16x2(va.x - __uint_as_float(h01 << 16),
                               va.y - __uint_as_float(h01 & 0xffff0000u));
    uint32_t l23 = pack_bf16x2(va.z - __uint_as_float(h23 << 16),
                               va.w - __uint_as_float(h23 & 0xffff0000u));
    uint32_t l45 = pack_bf16x2(vb.x - __uint_as_float(h45 << 16),
                               vb.y - __uint_as_float(h45 & 0xffff0000u));
    uint32_t l67 = pack_bf16x2(vb.z - __uint_as_float(h67 << 16),
                               vb.w - __uint_as_float(h67 & 0xffff0000u));
    size_t d = (size_t)row * dpitch + coff + col;
    __stcs((uint4*)(dhi + d), make_uint4(h01, h23, h45, h67));
    __stcs((uint4*)(dlo + d), make_uint4(l01, l23, l45, l67));
}

// =============== bf16 3-pass HMMA GEMM, 64x128 tile (unchanged core) ===============
#define STAGE_E 26624
#define STAGE_B (STAGE_E*2)
#define TG_SMEM (2*STAGE_B)

__global__ void __launch_bounds__(256, 2) tgemm_kernel(
    const __nv_bfloat16* __restrict__ aH, const __nv_bfloat16* __restrict__ aL,
    const __nv_bfloat16* __restrict__ bHp, const __nv_bfloat16* __restrict__ bLp,
    int ldb, float* __restrict__ C, int ldc,
    const float* __restrict__ res, const float* __restrict__ rowscale, int gather)
{
    extern __shared__ __nv_bfloat16 smb[];
    __shared__ int   tok[64];
    __shared__ float scl[64];
    int row0 = blockIdx.y * 64;
    int n0   = blockIdx.x * 128;
    int tid  = threadIdx.x;

    if (gather) {
        int e = blockIdx.z;
        int count = g_cnt[e];
        if (row0 >= count) return;
        bHp += (size_t)e * 2048 * ldb;
        bLp += (size_t)e * 2048 * ldb;
        if (tid < 64) {
            int r = row0 + tid;
            int t = (r < count) ? g_list[e * Sm + r] : -1;
            tok[tid] = t;
            scl[tid] = (t >= 0 && rowscale) ? rowscale[t] : 1.0f;
        }
    } else {
        if (tid < 64) { tok[tid] = row0 + tid; scl[tid] = 1.0f; }
    }
    __syncthreads();

    uint32_t smbase = smem_u32(smb);
    int lane = tid & 31, wid = tid >> 5;
    int gr = lane >> 2, tg = lane & 3;
    int wm = wid >> 2, wn = wid & 3;

    float acc[2][4][4];
#pragma unroll
    for (int i = 0; i < 2; i++)
#pragma unroll
        for (int j = 0; j < 4; j++)
#pragma unroll
            for (int r = 0; r < 4; r++) acc[i][j][r] = 0.f;

    auto copy_stage = [&](int st) {
        uint32_t base = smbase + (uint32_t)(st & 1) * STAGE_B;
        int k0 = st * 64;
#pragma unroll
        for (int pl = 0; pl < 2; pl++) {
            const __nv_bfloat16* asrc = pl ? aL : aH;
            uint32_t d0 = base + (pl ? 4608 : 0) * 2;
#pragma unroll
            for (int it = 0; it < 2; it++) {
                int idx = it * 256 + tid;
                int row = idx >> 3, ch = idx & 7;
                int t = tok[row];
                int grow = t < 0 ? 0 : t;
                cpa16(d0 + (uint32_t)(row * 72 + ch * 8) * 2,
                      asrc + (size_t)grow * 2048 + k0 + ch * 8);
            }
        }
#pragma unroll
        for (int pl = 0; pl < 2; pl++) {
            const __nv_bfloat16* bsrc = pl ? bLp : bHp;
            uint32_t d0 = base + (pl ? 17920 : 9216) * 2;
#pragma unroll
            for (int it = 0; it < 4; it++) {
                int idx = it * 256 + tid;
                int row = idx >> 4, ch = idx & 15;
                cpa16(d0 + (uint32_t)(row * 136 + ch * 8) * 2,
                      bsrc + (size_t)(k0 + row) * ldb + n0 + ch * 8);
            }
        }
        CPA_COMMIT();
    };

    copy_stage(0);
    int lr = lane & 15;
    int lc8 = (lane & 16) >> 1;

    for (int st = 0; st < 32; st++) {
        if (st + 1 < 32) { copy_stage(st + 1); CPA_WAIT1(); }
        else             { CPA_WAIT0(); }
        __syncthreads();
        uint32_t base = smbase + (uint32_t)(st & 1) * STAGE_B;
        uint32_t AHb = base, ALb = base + 9216;
        uint32_t BHb = base + 18432, BLb = base + 35840;
#pragma unroll
        for (int ks = 0; ks < 4; ks++) {
            uint32_t fAH[2][4], fAL[2][4], fBH[4][2], fBL[4][2];
#pragma unroll
            for (int mt = 0; mt < 2; mt++) {
                uint32_t ao = (uint32_t)((wm * 32 + mt * 16 + lr) * 72 + ks * 16 + lc8) * 2;
                ldm_x4(fAH[mt], AHb + ao);
                ldm_x4(fAL[mt], ALb + ao);
            }
#pragma unroll
            for (int half = 0; half < 2; half++) {
                int brow = ks * 16 + lr;
                int bcol = wn * 32 + half * 16 + lc8;
                uint32_t bo = (uint32_t)(brow * 136 + bcol) * 2;
                uint32_t rH[4], rL[4];
                ldm_x4t(rH, BHb + bo);
                ldm_x4t(rL, BLb + bo);
                fBH[half*2][0] = rH[0]; fBH[half*2][1] = rH[1];
                fBH[half*2+1][0] = rH[2]; fBH[half*2+1][1] = rH[3];
                fBL[half*2][0] = rL[0]; fBL[half*2][1] = rL[1];
                fBL[half*2+1][0] = rL[2]; fBL[half*2+1][1] = rL[3];
            }
#pragma unroll
            for (int mt = 0; mt < 2; mt++)
#pragma unroll
                for (int nt = 0; nt < 4; nt++) {
                    mma16816(acc[mt][nt], fAH[mt], fBH[nt]);
                    mma16816(acc[mt][nt], fAH[mt], fBL[nt]);
                    mma16816(acc[mt][nt], fAL[mt], fBH[nt]);
                }
        }
        __syncthreads();
    }

#pragma unroll
    for (int mt = 0; mt < 2; mt++) {
        int r1 = wm * 32 + mt * 16 + gr;
        int r2 = r1 + 8;
        int t1 = tok[r1], t2 = tok[r2];
        float s1 = scl[r1], s2 = scl[r2];
#pragma unroll
        for (int nt = 0; nt < 4; nt++) {
            int col = n0 + wn * 32 + nt * 8 + tg * 2;
            if (t1 >= 0) {
                float2 o = make_float2(acc[mt][nt][0] * s1, acc[mt][nt][1] * s1);
                if (res) {
                    float2 rv = *(const float2*)(res + (size_t)t1 * ldc + col);
                    o.x += rv.x; o.y += rv.y;
                }
                *(float2*)(C + (size_t)t1 * ldc + col) = o;
            }
            if (t2 >= 0) {
                float2 o = make_float2(acc[mt][nt][2] * s2, acc[mt][nt][3] * s2);
                if (res) {
                    float2 rv = *(const float2*)(res + (size_t)t2 * ldc + col);
                    o.x += rv.x; o.y += rv.y;
                }
                *(float2*)(C + (size_t)t2 * ldc + col) = o;
            }
        }
    }
}

// =============== attention scores via HMMA: S[h,i,j], 64x128 tile, K=128 ===============
// smem (elems): QH@0 [64][136], QL@8704, KH@17408 [128][136], KL@34816
#define SC_SMEM (52224*2)

__global__ void __launch_bounds__(256, 2) scores_mma_kernel(
    const __nv_bfloat16* __restrict__ qh, const __nv_bfloat16* __restrict__ ql,
    const __nv_bfloat16* __restrict__ kh, const __nv_bfloat16* __restrict__ kl,
    float* __restrict__ sc)
{
    extern __shared__ __nv_bfloat16 smb[];
    int h = blockIdx.z;
    int row0 = blockIdx.y * 64;
    int n0 = blockIdx.x * 128;
    int tid = threadIdx.x, lane = tid & 31, wid = tid >> 5;
    int gr = lane >> 2, tg = lane & 3;
    int wm = wid >> 2, wn = wid & 3;
    uint32_t base = smem_u32(smb);

    // stage Q (64 x 128) and K (128 x 128), both planes
#pragma unroll
    for (int pl = 0; pl < 2; pl++) {
        const __nv_bfloat16* src = pl ? ql : qh;
        uint32_t d0 = base + (pl ? 8704u : 0u) * 2;
#pragma unroll
        for (int it = 0; it < 4; it++) {
            int idx = it * 256 + tid;
            int r = idx >> 4, ch = idx & 15;
            cpa16(d0 + (uint32_t)(r * 136 + ch * 8) * 2,
                  src + (size_t)(row0 + r) * 2048 + h * 128 + ch * 8);
        }
    }
#pragma unroll
    for (int pl = 0; pl < 2; pl++) {
        const __nv_bfloat16* src = pl ? kl : kh;
        uint32_t d0 = base + (pl ? 34816u : 17408u) * 2;
#pragma unroll
        for (int it = 0; it < 8; it++) {
            int idx = it * 256 + tid;
            int r = idx >> 4, ch = idx & 15;
            cpa16(d0 + (uint32_t)(r * 136 + ch * 8) * 2,
                  src + (size_t)(n0 + r) * 512 + (h >> 2) * 128 + ch * 8);
        }
    }
    CPA_COMMIT(); CPA_WAIT0();
    __syncthreads();

    float acc[2][4][4];
#pragma unroll
    for (int i = 0; i < 2; i++)
#pragma unroll
        for (int j = 0; j < 4; j++)
#pragma unroll
            for (int r = 0; r < 4; r++) acc[i][j][r] = 0.f;

    int lr = lane & 15, lc8 = (lane & 16) >> 1;
    uint32_t QHb = base, QLb = base + 17408;  // bytes = elems*2: 8704*2
    uint32_t KHb = base + 34816, KLb = base + 69632;

#pragma unroll
    for (int ks = 0; ks < 8; ks++) {
        uint32_t fAH[2][4], fAL[2][4], fBH[4][2], fBL[4][2];
#pragma unroll
        for (int mt = 0; mt < 2; mt++) {
            uint32_t ao = (uint32_t)((wm * 32 + mt * 16 + lr) * 136 + ks * 16 + lc8) * 2;
            ldm_x4(fAH[mt], QHb + ao);
            ldm_x4(fAL[mt], QLb + ao);
        }
#pragma unroll
        for (int half = 0; half < 2; half++) {
            uint32_t bo = (uint32_t)((wn * 32 + half * 16 + lr) * 136 + ks * 16 + lc8) * 2;
            uint32_t rH[4], rL[4];
            ldm_x4(rH, KHb + bo);
            ldm_x4(rL, KLb + bo);
            fBH[half*2][0] = rH[0]; fBH[half*2][1] = rH[2];
            fBH[half*2+1][0] = rH[1]; fBH[half*2+1][1] = rH[3];
            fBL[half*2][0] = rL[0]; fBL[half*2][1] = rL[2];
            fBL[half*2+1][0] = rL[1]; fBL[half*2+1][1] = rL[3];
        }
#pragma unroll
        for (int mt = 0; mt < 2; mt++)
#pragma unroll
            for (int nt = 0; nt < 4; nt++) {
                mma16816(acc[mt][nt], fAH[mt], fBH[nt]);
                mma16816(acc[mt][nt], fAH[mt], fBL[nt]);
                mma16816(acc[mt][nt], fAL[mt], fBH[nt]);
            }
    }

    const float scale = 0.0883883476483184405f;
    float* out = sc + (size_t)h * Sm * Sm;
#pragma unroll
    for (int mt = 0; mt < 2; mt++) {
        int r1 = row0 + wm * 32 + mt * 16 + gr;
        int r2 = r1 + 8;
#pragma unroll
        for (int nt = 0; nt < 4; nt++) {
            int col = n0 + wn * 32 + nt * 8 + tg * 2;
            *(float2*)(out + (size_t)r1 * Sm + col) =
                make_float2(acc[mt][nt][0] * scale, acc[mt][nt][1] * scale);
            *(float2*)(out + (size_t)r2 * Sm + col) =
                make_float2(acc[mt][nt][2] * scale, acc[mt][nt][3] * scale);
        }
    }
}

// =============== PV via HMMA: attn[i, h*128+d] = sum_j p[h,i,j] v[j,d] ===============
__global__ void __launch_bounds__(256, 2) pv_mma_kernel(
    const __nv_bfloat16* __restrict__ ph_, const __nv_bfloat16* __restrict__ pl_,
    const __nv_bfloat16* __restrict__ vh, const __nv_bfloat16* __restrict__ vl,
    __nv_bfloat16* __restrict__ outh, __nv_bfloat16* __restrict__ outl)
{
    extern __shared__ __nv_bfloat16 smb[];
    int h = blockIdx.y;
    int row0 = blockIdx.x * 64;
    int kvoff = (h >> 2) * 128;
    int tid = threadIdx.x, lane = tid & 31, wid = tid >> 5;
    int gr = lane >> 2, tg = lane & 3;
    int wm = wid >> 2, wn = wid & 3;
    uint32_t smbase = smem_u32(smb);

    float acc[2][4][4];
#pragma unroll
    for (int i = 0; i < 2; i++)
#pragma unroll
        for (int j = 0; j < 4; j++)
#pragma unroll
            for (int r = 0; r < 4; r++) acc[i][j][r] = 0.f;

    auto copy_stage = [&](int st) {
        uint32_t base = smbase + (uint32_t)(st & 1) * STAGE_B;
        int k0 = st * 64;
#pragma unroll
        for (int pl = 0; pl < 2; pl++) {
            const __nv_bfloat16* asrc = pl ? pl_ : ph_;
            uint32_t d0 = base + (pl ? 4608 : 0) * 2;
#pragma unroll
            for (int it = 0; it < 2; it++) {
                int idx = it * 256 + tid;
                int row = idx >> 3, ch = idx & 7;
                cpa16(d0 + (uint32_t)(row * 72 + ch * 8) * 2,
                      asrc + ((size_t)h * Sm + row0 + row) * Sm + k0 + ch * 8);
            }
        }
#pragma unroll
        for (int pl = 0; pl < 2; pl++) {
            const __nv_bfloat16* bsrc = pl ? vl : vh;
            uint32_t d0 = base + (pl ? 17920 : 9216) * 2;
#pragma unroll
            for (int it = 0; it < 4; it++) {
                int idx = it * 256 + tid;
                int row = idx >> 4, ch = idx & 15;
                cpa16(d0 + (uint32_t)(row * 136 + ch * 8) * 2,
                      bsrc + (size_t)(k0 + row) * 512 + kvoff + ch * 8);
            }
        }
        CPA_COMMIT();
    };

    copy_stage(0);
    int lr = lane & 15, lc8 = (lane & 16) >> 1;

    for (int st = 0; st < 8; st++) {
        if (st + 1 < 8) { copy_stage(st + 1); CPA_WAIT1(); }
        else            { CPA_WAIT0(); }
        __syncthreads();
        uint32_t base = smbase + (uint32_t)(st & 1) * STAGE_B;
        uint32_t AHb = base, ALb = base + 9216;
        uint32_t BHb = base + 18432, BLb = base + 35840;
#pragma unroll
        for (int ks = 0; ks < 4; ks++) {
            uint32_t fAH[2][4], fAL[2][4], fBH[4][2], fBL[4][2];
#pragma unroll
            for (int mt = 0; mt < 2; mt++) {
                uint32_t ao = (uint32_t)((wm * 32 + mt * 16 + lr) * 72 + ks * 16 + lc8) * 2;
                ldm_x4(fAH[mt], AHb + ao);
                ldm_x4(fAL[mt], ALb + ao);
            }
#pragma unroll
            for (int half = 0; half < 2; half++) {
                uint32_t bo = (uint32_t)((ks * 16 + lr) * 136 + wn * 32 + half * 16 + lc8) * 2;
                uint32_t rH[4], rL[4];
                ldm_x4t(rH, BHb + bo);
                ldm_x4t(rL, BLb + bo);
                fBH[half*2][0] = rH[0]; fBH[half*2][1] = rH[1];
                fBH[half*2+1][0] = rH[2]; fBH[half*2+1][1] = rH[3];
                fBL[half*2][0] = rL[0]; fBL[half*2][1] = rL[1];
                fBL[half*2+1][0] = rL[2]; fBL[half*2+1][1] = rL[3];
            }
#pragma unroll
            for (int mt = 0; mt < 2; mt++)
#pragma unroll
                for (int nt = 0; nt < 4; nt++) {
                    mma16816(acc[mt][nt], fAH[mt], fBH[nt]);
                    mma16816(acc[mt][nt], fAH[mt], fBL[nt]);
                    mma16816(acc[mt][nt], fAL[mt], fBH[nt]);
                }
        }
        __syncthreads();
    }

#pragma unroll
    for (int mt = 0; mt < 2; mt++) {
        int r1 = row0 + wm * 32 + mt * 16 + gr;
        int r2 = r1 + 8;
#pragma unroll
        for (int nt = 0; nt < 4; nt++) {
            int col = h * 128 + wn * 32 + nt * 8 + tg * 2;
            float v0 = acc[mt][nt][0], v1 = acc[mt][nt][1];
            float v2 = acc[mt][nt][2], v3 = acc[mt][nt][3];
            uint32_t h01 = pack_bf16x2(v0, v1);
            uint32_t l01 = pack_bf16x2(v0 - __uint_as_float(h01 << 16),
                                       v1 - __uint_as_float(h01 & 0xffff0000u));
            uint32_t h23 = pack_bf16x2(v2, v3);
            uint32_t l23 = pack_bf16x2(v2 - __uint_as_float(h23 << 16),
                                       v3 - __uint_as_float(h23 & 0xffff0000u));
            *(uint32_t*)(outh + (size_t)r1 * 2048 + col) = h01;
            *(uint32_t*)(outl + (size_t)r1 * 2048 + col) = l01;
            *(uint32_t*)(outh + (size_t)r2 * 2048 + col) = h23;
            *(uint32_t*)(outl + (size_t)r2 * 2048 + col) = l23;
        }
    }
}

// ---------------- small kernels ----------------
__global__ void rmsnorm_kernel(const float* __restrict__ in, const float* __restrict__ w,
                               float* __restrict__ outf,
                               __nv_bfloat16* __restrict__ outh,
                               __nv_bfloat16* __restrict__ outl) {
    int t = blockIdx.x;
    const float* row = in + (size_t)t * Dm;
    float s = 0.f;
    for (int d = threadIdx.x; d < Dm; d += 256) { float v = row[d]; s += v * v; }
    __shared__ float red[256];
    red[threadIdx.x] = s; __syncthreads();
    for (int off = 128; off > 0; off >>= 1) {
        if (threadIdx.x < off) red[threadIdx.x] += red[threadIdx.x + off];
        __syncthreads();
    }
    float r = rsqrtf(red[0] / (float)Dm + 1e-5f);
    for (int d = threadIdx.x; d < Dm; d += 256) {
        float v = row[d] * r * w[d];
        if (outf) outf[(size_t)t * Dm + d] = v;
        split_store(v, outh, outl, (size_t)t * Dm + d);
    }
}

// rope + split q/k/v into bf16 planes
__global__ void rope_planes_kernel(const float* __restrict__ qkv, const int* __restrict__ pos_ids,
                                   __nv_bfloat16* qh, __nv_bfloat16* ql,
                                   __nv_bfloat16* kh, __nv_bfloat16* kl,
                                   __nv_bfloat16* vh, __nv_bfloat16* vl) {
    int t = blockIdx.x;
    float p = (float)pos_ids[t];
    for (int idx = threadIdx.x; idx < (Hn + HKVn) * 64; idx += blockDim.x) {
        int head = idx >> 6;
        int i = idx & 63;
        float inv = powf(500000.0f, -(float)i / 64.0f);
        float f = p * inv;
        float sn, cs;
        sincosf(f, &sn, &cs);
        if (head < Hn) {
            const float* src = qkv + (size_t)t * QKVP + head * DHn;
            float x1 = src[i], x2 = src[i + 64];
            size_t d = (size_t)t * Dm + head * DHn + i;
            split_store(x1 * cs - x2 * sn, qh, ql, d);
            split_store(x2 * cs + x1 * sn, qh, ql, d + 64);
        } else {
            int kvh = head - Hn;
            const float* src = qkv + (size_t)t * QKVP + 2048 + kvh * DHn;
            float x1 = src[i], x2 = src[i + 64];
            size_t d = (size_t)t * 512 + kvh * DHn + i;
            split_store(x1 * cs - x2 * sn, kh, kl, d);
            split_store(x2 * cs + x1 * sn, kh, kl, d + 64);
        }
    }
    for (int idx = threadIdx.x; idx < 512; idx += blockDim.x) {
        float v = qkv[(size_t)t * QKVP + 2560 + idx];
        split_store(v, vh, vl, (size_t)t * 512 + idx);
    }
}

// softmax over fp32 scores -> bf16 hi/lo p planes
__global__ void softmax_kernel(const float* __restrict__ sc, const int* __restrict__ mask,
                               __nv_bfloat16* __restrict__ ph, __nv_bfloat16* __restrict__ pl) {
    int i = blockIdx.x;
    int h = blockIdx.y;
    const float* row = sc + ((size_t)h * Sm + i) * Sm;
    int tid = threadIdx.x;
    int j0 = tid, j1 = tid + 256;
    float s0 = (j0 <= i && mask[j0] > 0) ? row[j0] : -1e9f;
    float s1 = (j1 <= i && mask[j1] > 0) ? row[j1] : -1e9f;
    __shared__ float red[256];
    red[tid] = fmaxf(s0, s1); __syncthreads();
    for (int off = 128; off > 0; off >>= 1) {
        if (tid < off) red[tid] = fmaxf(red[tid], red[tid + off]);
        __syncthreads();
    }
    float m = red[0];
    __syncthreads();
    float e0 = expf(s0 - m), e1 = expf(s1 - m);
    red[tid] = e0 + e1; __syncthreads();
    for (int off = 128; off > 0; off >>= 1) {
        if (tid < off) red[tid] += red[tid + off];
        __syncthreads();
    }
    float inv = 1.f / red[0];
    size_t base = ((size_t)h * Sm + i) * Sm;
    split_store(e0 * inv, ph, pl, base + j0);
    split_store(e1 * inv, ph, pl, base + j1);
}

__global__ void router_kernel(const float* __restrict__ x2, const float* __restrict__ rw,
                              int* __restrict__ topidx, float* __restrict__ topscore) {
    int t = blockIdx.x;
    int w = threadIdx.x >> 5, lane = threadIdx.x & 31;
    float s = 0.f;
    for (int d = lane; d < Dm; d += 32)
        s += x2[(size_t)t * Dm + d] * rw[d * En + w];
    for (int off = 16; off; off >>= 1) s += __shfl_down_sync(0xffffffff, s, off);
    __shared__ float logits[En];
    if (lane == 0) logits[w] = s;
    __syncthreads();
    if (threadIdx.x == 0) {
        int best = 0; float bv = logits[0];
        for (int e = 1; e < En; e++) if (logits[e] > bv) { bv = logits[e]; best = e; }
        topidx[t] = best;
        topscore[t] = 1.f / (1.f + expf(-bv));
    }
}

__global__ void dispatch_kernel(const int* __restrict__ topidx) {
    int t = threadIdx.x;
    if (t < En) g_cnt[t] = 0;
    __syncthreads();
    int e = topidx[t];
    int pos = atomicAdd(&g_cnt[e], 1);
    g_list[e * Sm + pos] = t;
}

__global__ void silumul_kernel(const float* __restrict__ gu,
                               __nv_bfloat16* __restrict__ outh,
                               __nv_bfloat16* __restrict__ outl) {
    int i = blockIdx.x * 256 + threadIdx.x;
    int t = i >> 11, j = i & 2047;
    float g = gu[(size_t)t * 4096 + j];
    float u = gu[(size_t)t * 4096 + 2048 + j];
    float a = (g / (1.f + expf(-g))) * u;
    split_store(a, outh, outl, (size_t)i);
}

__global__ void add3_kernel(const float* __restrict__ a, const float* __restrict__ b,
                            const float* __restrict__ c, float* __restrict__ out) {
    int i = blockIdx.x * 256 + threadIdx.x;
    out[i] = a[i] + b[i] + c[i];
}

// ---------------- launch ----------------
#define GSYM(p, s) cudaGetSymbolAddress((void**)&p, s)

extern "C" void kernel_launch(void* const* d_in, const int* in_sizes, int n_in,
                              void* d_out, int out_size) {
    const float* hidden   = (const float*)d_in[0];
    const int*   amask    = (const int*)  d_in[1];
    const int*   pos      = (const int*)  d_in[2];
    const float* attn_nw  = (const float*)d_in[3];
    const float* wq       = (const float*)d_in[4];
    const float* wk       = (const float*)d_in[5];
    const float* wv       = (const float*)d_in[6];
    const float* wo       = (const float*)d_in[7];
    const float* ffn_nw   = (const float*)d_in[8];
    const float* router_w = (const float*)d_in[9];
    const float* w_gate   = (const float*)d_in[10];
    const float* w_up     = (const float*)d_in[11];
    const float* w_down   = (const float*)d_in[12];
    const float* ws_gate  = (const float*)d_in[13];
    const float* ws_up    = (const float*)d_in[14];
    const float* ws_down  = (const float*)d_in[15];
    float* out = (float*)d_out;

    float *pqkv, *psc, *phf, *px2f, *pgu, *psgu, *prouted, *pshared, *pts;
    int *pti;
    __nv_bfloat16 *pxh, *pxl, *path, *patl, *px2h, *px2l, *pach, *pacl, *psah, *psal;
    __nv_bfloat16 *pqh, *pql, *pkh, *pkl, *pvh, *pvl, *pph, *ppl;
    __nv_bfloat16 *pwqkvh, *pwqkvl, *pwoh, *pwol, *pguh, *pgul, *pdnh, *pdnl,
                  *psguh, *psgul, *psdnh, *psdnl;
    GSYM(pqkv, g_qkv); GSYM(psc, g_scores); GSYM(phf, g_h); GSYM(px2f, g_x2f);
    GSYM(pgu, g_gu); GSYM(psgu, g_sgu); GSYM(prouted, g_routed); GSYM(pshared, g_shared);
    GSYM(pti, g_topidx); GSYM(pts, g_topscore);
    GSYM(pxh, x_h); GSYM(pxl, x_l); GSYM(path, at_h); GSYM(patl, at_l);
    GSYM(px2h, x2_h); GSYM(px2l, x2_l); GSYM(pach, ac_h); GSYM(pacl, ac_l);
    GSYM(psah, sa_h); GSYM(psal, sa_l);
    GSYM(pqh, q_h); GSYM(pql, q_l); GSYM(pkh, k_h); GSYM(pkl, k_l);
    GSYM(pvh, v_h); GSYM(pvl, v_l); GSYM(pph, p_h); GSYM(ppl, p_l);
    GSYM(pwqkvh, cw_qkv_h); GSYM(pwqkvl, cw_qkv_l);
    GSYM(pwoh, cw_wo_h); GSYM(pwol, cw_wo_l);
    GSYM(pguh, cw_gu_h); GSYM(pgul, cw_gu_l);
    GSYM(pdnh, cw_dn_h); GSYM(pdnl, cw_dn_l);
    GSYM(psguh, cw_sgu_h); GSYM(psgul, cw_sgu_l);
    GSYM(psdnh, cw_sdn_h); GSYM(psdnl, cw_sdn_l);

    cudaFuncSetAttribute(tgemm_kernel, cudaFuncAttributeMaxDynamicSharedMemorySize, TG_SMEM);
    cudaFuncSetAttribute(scores_mma_kernel, cudaFuncAttributeMaxDynamicSharedMemorySize, SC_SMEM);
    cudaFuncSetAttribute(pv_mma_kernel, cudaFuncAttributeMaxDynamicSharedMemorySize, TG_SMEM);

    // --- weight conversion ---
    convw_kernel<<<2048, 256>>>(wq, pwqkvh, pwqkvl, 2048, 3072, 0,    2048*2048/8);
    convw_kernel<<<512,  256>>>(wk, pwqkvh, pwqkvl, 512,  3072, 2048, 2048*512/8);
    convw_kernel<<<512,  256>>>(wv, pwqkvh, pwqkvl, 512,  3072, 2560, 2048*512/8);
    convw_kernel<<<2048, 256>>>(wo, pwoh, pwol, 2048, 2048, 0, 2048*2048/8);
    convw_kernel<<<16384, 256>>>(w_gate, pguh, pgul, 2048, 4096, 0,    8*2048*2048/8);
    convw_kernel<<<16384, 256>>>(w_up,   pguh, pgul, 2048, 4096, 2048, 8*2048*2048/8);
    convw_kernel<<<16384, 256>>>(w_down, pdnh, pdnl, 2048, 2048, 0,    8*2048*2048/8);
    convw_kernel<<<2048, 256>>>(ws_gate, psguh, psgul, 2048, 4096, 0,    2048*2048/8);
    convw_kernel<<<2048, 256>>>(ws_up,   psguh, psgul, 2048, 4096, 2048, 2048*2048/8);
    convw_kernel<<<2048, 256>>>(ws_down, psdnh, psdnl, 2048, 2048, 0, 2048*2048/8);

    // --- attention block ---
    rmsnorm_kernel<<<Sm, 256>>>(hidden, attn_nw, nullptr, pxh, pxl);
    tgemm_kernel<<<dim3(24, 8), 256, TG_SMEM>>>(pxh, pxl, pwqkvh, pwqkvl, 3072,
                                                pqkv, 3072, nullptr, nullptr, 0);
    rope_planes_kernel<<<Sm, 256>>>(pqkv, pos, pqh, pql, pkh, pkl, pvh, pvl);
    scores_mma_kernel<<<dim3(4, 8, Hn), 256, SC_SMEM>>>(pqh, pql, pkh, pkl, psc);
    softmax_kernel<<<dim3(Sm, Hn), 256>>>(psc, amask, pph, ppl);
    pv_mma_kernel<<<dim3(8, Hn), 256, TG_SMEM>>>(pph, ppl, pvh, pvl, path, patl);
    tgemm_kernel<<<dim3(16, 8), 256, TG_SMEM>>>(path, patl, pwoh, pwol, 2048,
                                                phf, 2048, hidden, nullptr, 0);

    // --- MoE block ---
    rmsnorm_kernel<<<Sm, 256>>>(phf, ffn_nw, px2f, px2h, px2l);
    router_kernel<<<Sm, 256>>>(px2f, router_w, pti, pts);
    dispatch_kernel<<<1, Sm>>>(pti);
    tgemm_kernel<<<dim3(32, 8, En), 256, TG_SMEM>>>(px2h, px2l, pguh, pgul, 4096,
                                                    pgu, 4096, nullptr, pts, 1);
    silumul_kernel<<<(Sm * Dm) / 256, 256>>>(pgu, pach, pacl);
    tgemm_kernel<<<dim3(16, 8, En), 256, TG_SMEM>>>(pach, pacl, pdnh, pdnl, 2048,
                                                    prouted, 2048, nullptr, nullptr, 1);

    // shared expert
    tgemm_kernel<<<dim3(32, 8), 256, TG_SMEM>>>(px2h, px2l, psguh, psgul, 4096,
                                                psgu, 4096, nullptr, nullptr, 0);
    silumul_kernel<<<(Sm * Dm) / 256, 256>>>(psgu, psah, psal);
    tgemm_kernel<<<dim3(16, 8), 256, TG_SMEM>>>(psah, psal, psdnh, psdnl, 2048,
                                                pshared, 2048, nullptr, nullptr, 0);

    // final: out = h + routed + shared
    add3_kernel<<<(Sm * Dm) / 256, 256>>>(phf, prouted, pshared, out);
}